// round 12
// baseline (speedup 1.0000x reference)
#include <cuda_runtime.h>
#include <math.h>

#define BB    16
#define TT    64
#define IND   256
#define HH    512
#define NN    256
#define WWD   64
#define RR    4
#define OUTD  256
#define ITFD  471
#define G4H   2048   // 4*H
#define RLEN  768    // combined activation row: 256 (rw) + 512 (h)
#define NCH   32     // link row-chunks per batch (8 rows each)

// interface vector offsets
#define O_RK 0
#define O_RS 256
#define O_WK 260
#define O_WS 324
#define O_ER 325
#define O_WV 389
#define O_FG 453
#define O_AG 457
#define O_WG 458
#define O_MO 459
#define EPSF 1e-6f

// -------------------- persistent state --------------------
__device__ __align__(16) float g_act[2][BB * RLEN];   // [rw(256) | h(512)] per batch
__device__ __align__(16) float g_c[BB * HH];
__device__ __align__(16) float g_M[BB * NN * WWD];
__device__ __align__(16) float g_usage[BB * NN];
__device__ __align__(16) float g_link[BB * NN * NN];
__device__ __align__(16) float g_prec[2][BB * NN];
__device__ __align__(16) float g_wr[BB * RR * NN];
__device__ __align__(16) float g_ww[BB * NN];
__device__ __align__(16) float g_itf[BB * ITFD];
__device__ __align__(16) float g_hall[TT * BB * HH];
__device__ __align__(16) float g_rwall[TT * BB * RR * WWD];
__device__ __align__(16) float g_WintT[ITFD * HH];
__device__ __align__(16) float g_bwdP[BB * NCH * RR * NN];
__device__ __align__(16) float g_fwd[BB * RR * NN];
__device__ __align__(16) float g_Wrec[G4H * RLEN];       // [2048][768] = [W_ih(rw cols) | W_hh]
__device__ __align__(16) float g_gatesx[TT * BB * G4H];  // x-part of gates + biases

// -------------------- helpers --------------------
__device__ __forceinline__ float sigf(float x) { return 1.f / (1.f + expf(-x)); }
__device__ __forceinline__ float softplusf(float x) {
    return fmaxf(x, 0.f) + log1pf(expf(-fabsf(x)));
}
__device__ __forceinline__ float oneplusf(float x) { return 1.f + softplusf(x); }

__device__ __forceinline__ float blk_max256(float v, float* red, int tid) {
    red[tid] = v; __syncthreads();
    for (int s = 128; s > 0; s >>= 1) {
        if (tid < s) red[tid] = fmaxf(red[tid], red[tid + s]);
        __syncthreads();
    }
    float r = red[0]; __syncthreads();
    return r;
}
__device__ __forceinline__ float blk_sum256(float v, float* red, int tid) {
    red[tid] = v; __syncthreads();
    for (int s = 128; s > 0; s >>= 1) {
        if (tid < s) red[tid] = red[tid] + red[tid + s];
        __syncthreads();
    }
    float r = red[0]; __syncthreads();
    return r;
}

__device__ __forceinline__ void red4op(float v[4], bool domax, volatile float* red) {
    int tid = threadIdx.x;
    #pragma unroll
    for (int r = 0; r < 4; r++)
        #pragma unroll
        for (int o = 16; o; o >>= 1) {
            float u = __shfl_xor_sync(0xffffffffu, v[r], o);
            v[r] = domax ? fmaxf(v[r], u) : (v[r] + u);
        }
    if ((tid & 31) == 0) {
        int w = tid >> 5;
        red[w * 4 + 0] = v[0]; red[w * 4 + 1] = v[1];
        red[w * 4 + 2] = v[2]; red[w * 4 + 3] = v[3];
    }
    __syncthreads();
    if (tid == 0) {
        #pragma unroll
        for (int r = 0; r < 4; r++) {
            float a = red[r];
            for (int w = 1; w < 8; w++) {
                float u = red[w * 4 + r];
                a = domax ? fmaxf(a, u) : (a + u);
            }
            red[40 + r] = a;
        }
    }
    __syncthreads();
    v[0] = red[40]; v[1] = red[41]; v[2] = red[42]; v[3] = red[43];
    __syncthreads();
}

// -------------------- prep kernels (one-time) --------------------
__global__ void k_transpose(const float* __restrict__ Wint) {
    int idx = blockIdx.x * 256 + threadIdx.x;
    if (idx < ITFD * HH) {
        int c = idx / HH;
        int k = idx - c * HH;
        g_WintT[idx] = Wint[(size_t)k * ITFD + c];
    }
}

__global__ void k_prep_wrec(const float* __restrict__ Wih,
                            const float* __restrict__ Whh) {
    int idx = blockIdx.x * 256 + threadIdx.x;
    if (idx < G4H * RLEN) {
        int row = idx / RLEN;
        int c = idx - row * RLEN;
        g_Wrec[idx] = (c < 256) ? Wih[(size_t)row * 512 + 256 + c]
                                : Whh[(size_t)row * 512 + (c - 256)];
    }
}

__global__ void k_gatesx(const float* __restrict__ x,
                         const float* __restrict__ Wih,
                         const float* __restrict__ bih,
                         const float* __restrict__ bhh) {
    __shared__ float As[32][33];
    __shared__ float Bs[32][33];
    int tx = threadIdx.x & 15, ty = threadIdx.x >> 4;
    int m0 = blockIdx.x * 32, n0 = blockIdx.y * 32;
    float a00 = 0.f, a01 = 0.f, a10 = 0.f, a11 = 0.f;
    for (int kt = 0; kt < 256; kt += 32) {
        for (int l = threadIdx.x; l < 1024; l += 256) {
            int mi = l >> 5, ki = l & 31;
            As[mi][ki] = x[(size_t)(m0 + mi) * IND + kt + ki];
            Bs[mi][ki] = Wih[(size_t)(n0 + mi) * 512 + kt + ki];
        }
        __syncthreads();
        #pragma unroll 8
        for (int ki = 0; ki < 32; ki++) {
            float x0 = As[ty * 2][ki], x1 = As[ty * 2 + 1][ki];
            float w0 = Bs[tx * 2][ki], w1 = Bs[tx * 2 + 1][ki];
            a00 += x0 * w0; a01 += x0 * w1;
            a10 += x1 * w0; a11 += x1 * w1;
        }
        __syncthreads();
    }
    int m = m0 + ty * 2, n = n0 + tx * 2;
    float c0 = bih[n] + bhh[n], c1 = bih[n + 1] + bhh[n + 1];
    g_gatesx[(size_t)m * G4H + n] = a00 + c0;
    g_gatesx[(size_t)m * G4H + n + 1] = a01 + c1;
    g_gatesx[(size_t)(m + 1) * G4H + n] = a10 + c0;
    g_gatesx[(size_t)(m + 1) * G4H + n + 1] = a11 + c1;
}

// -------------------- K1: LSTM recurrent, smem-staged act ----------------------
// grid (512 j, 2 batch-groups), block 256.
// tid = warp*32 + kcw*8 + b8 ; kc = warp*4+kcw covers 24 cols; b8 in [0,8).
__global__ void __launch_bounds__(256) k_lstm(int t, int par) {
    __shared__ float sAct[8][772];     // padded rows, 16B-aligned stride
    __shared__ float sgate[4][8][8];   // [gate][warp][b8]
    __shared__ float gfin[4][8];
    int tid = threadIdx.x;
    int j  = blockIdx.x;
    int bg = blockIdx.y;               // batch group: batches bg*8 .. bg*8+7

    // stage 8 batches x 768 cols, coalesced
    for (int i = tid; i < 1536; i += 256) {     // 1536 float4
        int b = i / 192, q = i - (i / 192) * 192;
        float4 v = ((const float4*)(g_act[par] + (size_t)(bg * 8 + b) * RLEN))[q];
        *(float4*)&sAct[b][q * 4] = v;
    }
    __syncthreads();

    int warp = tid >> 5;
    int kcw  = (tid >> 3) & 3;
    int b8   = tid & 7;
    int c0   = (warp * 4 + kcw) * 24;

    const float4* a4  = (const float4*)&sAct[b8][c0];
    const float4* w04 = (const float4*)(g_Wrec + (size_t)(0 * HH + j) * RLEN + c0);
    const float4* w14 = (const float4*)(g_Wrec + (size_t)(1 * HH + j) * RLEN + c0);
    const float4* w24 = (const float4*)(g_Wrec + (size_t)(2 * HH + j) * RLEN + c0);
    const float4* w34 = (const float4*)(g_Wrec + (size_t)(3 * HH + j) * RLEN + c0);

    float acc0 = 0.f, acc1 = 0.f, acc2 = 0.f, acc3 = 0.f;
    #pragma unroll
    for (int q = 0; q < 6; q++) {
        float4 av = a4[q];
        float4 wv;
        wv = w04[q]; acc0 += av.x * wv.x + av.y * wv.y + av.z * wv.z + av.w * wv.w;
        wv = w14[q]; acc1 += av.x * wv.x + av.y * wv.y + av.z * wv.z + av.w * wv.w;
        wv = w24[q]; acc2 += av.x * wv.x + av.y * wv.y + av.z * wv.z + av.w * wv.w;
        wv = w34[q]; acc3 += av.x * wv.x + av.y * wv.y + av.z * wv.z + av.w * wv.w;
    }
    // combine the 4 kcw groups within each warp (lanes 8 and 16 apart)
    acc0 += __shfl_xor_sync(0xffffffffu, acc0, 8);
    acc1 += __shfl_xor_sync(0xffffffffu, acc1, 8);
    acc2 += __shfl_xor_sync(0xffffffffu, acc2, 8);
    acc3 += __shfl_xor_sync(0xffffffffu, acc3, 8);
    acc0 += __shfl_xor_sync(0xffffffffu, acc0, 16);
    acc1 += __shfl_xor_sync(0xffffffffu, acc1, 16);
    acc2 += __shfl_xor_sync(0xffffffffu, acc2, 16);
    acc3 += __shfl_xor_sync(0xffffffffu, acc3, 16);
    if ((tid & 24) == 0) {    // kcw==0 lanes (lane = b8)
        sgate[0][warp][b8] = acc0; sgate[1][warp][b8] = acc1;
        sgate[2][warp][b8] = acc2; sgate[3][warp][b8] = acc3;
    }
    __syncthreads();
    if (tid < 32) {
        int g = tid >> 3, bb = tid & 7;
        float s = 0.f;
        #pragma unroll
        for (int w2 = 0; w2 < 8; w2++) s += sgate[g][w2][bb];
        gfin[g][bb] = s;
    }
    __syncthreads();
    if (tid < 8) {
        int bb = bg * 8 + tid;
        const float* gx = g_gatesx + ((size_t)t * BB + bb) * G4H;
        float gi = gfin[0][tid] + gx[0 * HH + j];
        float gf = gfin[1][tid] + gx[1 * HH + j];
        float gg = gfin[2][tid] + gx[2 * HH + j];
        float go = gfin[3][tid] + gx[3 * HH + j];
        float cold = g_c[bb * HH + j];
        float cn = sigf(gf) * cold + sigf(gi) * tanhf(gg);
        float hn = sigf(go) * tanhf(cn);
        g_c[bb * HH + j] = cn;
        g_act[par ^ 1][bb * RLEN + 256 + j] = hn;
        g_hall[((size_t)t * BB + bb) * HH + j] = hn;
    }
}

// -------------------- K2: wide interface GEMV (grid 118, block 256) -------------
__global__ void __launch_bounds__(256) k_itf2(const float* __restrict__ bint, int par) {
    __shared__ float hS[16 * 512];
    int tid = threadIdx.x;
    for (int i = tid; i < 2048; i += 256) {      // 2048 float4
        int b = i >> 7, q = i & 127;
        ((float4*)hS)[i] = ((const float4*)(g_act[par ^ 1] + b * RLEN + 256))[q];
    }
    __syncthreads();

    int lane = tid & 31, w = tid >> 5;
    int cbase = blockIdx.x * 4;
    #pragma unroll
    for (int i = 0; i < 8; i++) {
        int task = i * 8 + w;
        int c = cbase + (task >> 4);
        int b = task & 15;
        if (c < ITFD) {
            const float4* w4 = (const float4*)(g_WintT + (size_t)c * HH);
            const float4* h4 = (const float4*)(hS + b * 512);
            float acc = 0.f;
            #pragma unroll
            for (int q = 0; q < 4; q++) {
                float4 wv = w4[lane + q * 32];
                float4 hv = h4[lane + q * 32];
                acc += wv.x * hv.x + wv.y * hv.y + wv.z * hv.z + wv.w * hv.w;
            }
            #pragma unroll
            for (int o = 16; o; o >>= 1) acc += __shfl_xor_sync(0xffffffffu, acc, o);
            if (lane == 0) g_itf[b * ITFD + c] = acc + bint[c];
        }
    }
}

// -------------------- K3: per-batch write addressing (grid 16) ------------------
__global__ void __launch_bounds__(256) k_write(int par) {
    int b = blockIdx.x;
    int tid = threadIdx.x;
    __shared__ float itfs[ITFD + 1];
    __shared__ float uval[NN];
    __shared__ int   uidx[NN];
    __shared__ float allocv[NN];
    __shared__ float red[NN];
    __shared__ float karr[WWD];
    __shared__ float sc_knorm, sc_beta;

    for (int i = tid; i < ITFD; i += 256) itfs[i] = g_itf[b * ITFD + i];
    __syncthreads();

    float fg0 = sigf(itfs[O_FG + 0]);
    float fg1 = sigf(itfs[O_FG + 1]);
    float fg2 = sigf(itfs[O_FG + 2]);
    float fg3 = sigf(itfs[O_FG + 3]);
    float ag  = sigf(itfs[O_AG]);
    float wg  = sigf(itfs[O_WG]);

    int n = tid;
    float psi = 1.f;
    psi *= (1.f - fg0 * g_wr[(b * RR + 0) * NN + n]);
    psi *= (1.f - fg1 * g_wr[(b * RR + 1) * NN + n]);
    psi *= (1.f - fg2 * g_wr[(b * RR + 2) * NN + n]);
    psi *= (1.f - fg3 * g_wr[(b * RR + 3) * NN + n]);
    float u = g_usage[b * NN + n];
    float wagg = g_ww[b * NN + n];  // NW=1
    float un = (u + wagg - u * wagg) * psi;
    g_usage[b * NN + n] = un;

    if (tid < WWD) karr[tid] = itfs[O_WK + tid];
    __syncthreads();
    if (tid == 0) {
        float ss = 0.f;
        for (int w = 0; w < WWD; w++) ss += karr[w] * karr[w];
        sc_knorm = sqrtf(ss) + EPSF;
        sc_beta  = oneplusf(itfs[O_WS]);
    }
    __syncthreads();

    float dot = 0.f, ss = 0.f;
    const float* Mrow = g_M + ((size_t)(b * NN) + n) * WWD;
    #pragma unroll 8
    for (int w = 0; w < WWD; w++) {
        float m = Mrow[w];
        dot += m * karr[w];
        ss += m * m;
    }
    float sim = (dot / sc_knorm) / (sqrtf(ss) + EPSF);
    float sco = sc_beta * sim;
    float mx = blk_max256(sco, red, tid);
    float e = expf(sco - mx);
    float sm = blk_sum256(e, red, tid);
    float cwv = e / sm;

    // stable bitonic sort ascending on (usage, index); shfl for jmp<32
    float v = un; int ix = tid;
    for (int k2 = 2; k2 <= NN; k2 <<= 1) {
        for (int jmp = k2 >> 1; jmp; jmp >>= 1) {
            bool up = ((tid & k2) == 0);
            float v2; int i2;
            if (jmp >= 32) {
                uval[tid] = v; uidx[tid] = ix;
                __syncthreads();
                v2 = uval[tid ^ jmp]; i2 = uidx[tid ^ jmp];
                __syncthreads();
            } else {
                v2 = __shfl_xor_sync(0xffffffffu, v, jmp);
                i2 = __shfl_xor_sync(0xffffffffu, ix, jmp);
            }
            bool lower = ((tid & jmp) == 0);
            bool iless = (v < v2) || (v == v2 && ix < i2);
            bool keep = (iless == (lower == up));
            if (!keep) { v = v2; ix = i2; }
        }
    }

    // exclusive product scan over sorted usage -> allocation
    {
        int lane = tid & 31, wid = tid >> 5;
        float p = v;
        #pragma unroll
        for (int o = 1; o < 32; o <<= 1) {
            float q = __shfl_up_sync(0xffffffffu, p, o);
            if (lane >= o) p *= q;
        }
        if (lane == 31) red[wid] = p;
        __syncthreads();
        if (tid == 0) {
            float a = 1.f;
            #pragma unroll
            for (int w = 0; w < 8; w++) { float q = red[w]; red[8 + w] = a; a *= q; }
        }
        __syncthreads();
        float tmp = __shfl_up_sync(0xffffffffu, p, 1);
        float exclw = (lane == 0) ? 1.f : tmp;
        float excl = red[8 + wid] * exclw;
        allocv[ix] = (1.f - v) * excl;
        __syncthreads();
    }

    float wwn = wg * (ag * allocv[tid] + (1.f - ag) * cwv);
    g_ww[b * NN + tid] = wwn;
    float wsum = blk_sum256(wwn, red, tid);
    float pold = g_prec[par][b * NN + tid];
    g_prec[par ^ 1][b * NN + tid] = (1.f - wsum) * pold + wwn;
}

// -------------------- K4: wide link+M update (grid 512 = 16b x 32ch) ------------
__global__ void __launch_bounds__(256) k_mem2(int par) {
    int blk = blockIdx.x;
    int b = blk >> 5, ch = blk & 31;     // 8 rows per chunk
    int tid = threadIdx.x;
    __shared__ float sww[NN];
    __shared__ float sprec[NN];
    __shared__ float wr4[4][NN];
    __shared__ float er[WWD];
    __shared__ float vv[WWD];
    __shared__ float tile[8][260];

    sww[tid]   = g_ww[b * NN + tid];
    sprec[tid] = g_prec[par][b * NN + tid];
    #pragma unroll
    for (int r = 0; r < RR; r++) wr4[r][tid] = g_wr[(b * RR + r) * NN + tid];
    if (tid < WWD) {
        er[tid] = sigf(g_itf[b * ITFD + O_ER + tid]);
        vv[tid] = sigf(g_itf[b * ITFD + O_WV + tid]);
    }
    __syncthreads();

    float wwj = sww[tid];
    float prj = sprec[tid];
    float bp0 = 0.f, bp1 = 0.f, bp2 = 0.f, bp3 = 0.f;
    float* lbase = g_link + (size_t)b * (NN * NN);
    #pragma unroll
    for (int ii = 0; ii < 8; ii++) {
        int i = ch * 8 + ii;
        float wwi = sww[i];
        float l = lbase[(size_t)i * NN + tid];
        float nv = (1.f - wwi - wwj) * l + wwi * prj;
        if (i == tid) nv = 0.f;
        lbase[(size_t)i * NN + tid] = nv;
        tile[ii][tid] = nv;
        bp0 += nv * wr4[0][i];
        bp1 += nv * wr4[1][i];
        bp2 += nv * wr4[2][i];
        bp3 += nv * wr4[3][i];
    }
    g_bwdP[((b * NCH + ch) * 4 + 0) * NN + tid] = bp0;
    g_bwdP[((b * NCH + ch) * 4 + 1) * NN + tid] = bp1;
    g_bwdP[((b * NCH + ch) * 4 + 2) * NN + tid] = bp2;
    g_bwdP[((b * NCH + ch) * 4 + 3) * NN + tid] = bp3;
    __syncthreads();

    // fwd: warp per row (8 warps, 8 rows)
    {
        int warp = tid >> 5, lane = tid & 31;
        int ii = warp;
        int i = ch * 8 + ii;
        float a0 = 0.f, a1 = 0.f, a2 = 0.f, a3 = 0.f;
        #pragma unroll
        for (int p = 0; p < 8; p++) {
            int jx = lane + p * 32;
            float lv = tile[ii][jx];
            a0 += lv * wr4[0][jx]; a1 += lv * wr4[1][jx];
            a2 += lv * wr4[2][jx]; a3 += lv * wr4[3][jx];
        }
        #pragma unroll
        for (int o = 16; o; o >>= 1) {
            a0 += __shfl_down_sync(0xffffffffu, a0, o);
            a1 += __shfl_down_sync(0xffffffffu, a1, o);
            a2 += __shfl_down_sync(0xffffffffu, a2, o);
            a3 += __shfl_down_sync(0xffffffffu, a3, o);
        }
        if (lane == 0) {
            g_fwd[(b * 4 + 0) * NN + i] = a0;
            g_fwd[(b * 4 + 1) * NN + i] = a1;
            g_fwd[(b * 4 + 2) * NN + i] = a2;
            g_fwd[(b * 4 + 3) * NN + i] = a3;
        }
    }

    // memory erase/write for rows [ch*8, ch*8+8): 8 rows x 64 cols, 2 cols/thread
    {
        int n = ch * 8 + (tid >> 5);
        int w0 = (tid & 31) * 2;
        float wwn = sww[n];
        float* Mp = g_M + ((size_t)(b * NN) + n) * WWD + w0;
        Mp[0] = Mp[0] * (1.f - wwn * er[w0 + 0]) + wwn * vv[w0 + 0];
        Mp[1] = Mp[1] * (1.f - wwn * er[w0 + 1]) + wwn * vv[w0 + 1];
    }
}

// -------------------- K5: per-batch read combine (grid 16) ----------------------
__global__ void __launch_bounds__(256) k_read2(int t, int par) {
    int b = blockIdx.x;
    int tid = threadIdx.x;
    __shared__ float kn[RR][WWD];
    __shared__ float wr_s[RR][NN];
    __shared__ float red[64];
    __shared__ float betas[RR], knorm[RR], mbv[RR], mfv[RR], mcv[RR];

    const float* itf = g_itf + (size_t)b * ITFD;

    {
        int r = tid >> 6, w = tid & 63;
        kn[r][w] = itf[O_RK + r * WWD + w];
    }
    __syncthreads();
    if (tid < RR) {
        float ss2 = 0.f;
        for (int w = 0; w < WWD; w++) ss2 += kn[tid][w] * kn[tid][w];
        knorm[tid] = sqrtf(ss2) + EPSF;
        betas[tid] = oneplusf(itf[O_RS + tid]);
        float m0 = itf[O_MO + tid * 3 + 0];
        float m1 = itf[O_MO + tid * 3 + 1];
        float m2 = itf[O_MO + tid * 3 + 2];
        float mxm = fmaxf(m0, fmaxf(m1, m2));
        float e0 = expf(m0 - mxm), e1 = expf(m1 - mxm), e2 = expf(m2 - mxm);
        float s = e0 + e1 + e2;
        mbv[tid] = e0 / s; mfv[tid] = e1 / s; mcv[tid] = e2 / s;
    }
    __syncthreads();

    const float* Mrow = g_M + ((size_t)(b * NN) + tid) * WWD;
    float d0 = 0.f, d1 = 0.f, d2 = 0.f, d3 = 0.f, ss2 = 0.f;
    #pragma unroll 8
    for (int w = 0; w < WWD; w++) {
        float m = Mrow[w];
        ss2 += m * m;
        d0 += m * kn[0][w]; d1 += m * kn[1][w]; d2 += m * kn[2][w]; d3 += m * kn[3][w];
    }
    float inv = 1.f / (sqrtf(ss2) + EPSF);
    float scv[4], m4[4];
    scv[0] = betas[0] * (d0 / knorm[0]) * inv;
    scv[1] = betas[1] * (d1 / knorm[1]) * inv;
    scv[2] = betas[2] * (d2 / knorm[2]) * inv;
    scv[3] = betas[3] * (d3 / knorm[3]) * inv;
    #pragma unroll
    for (int r = 0; r < 4; r++) m4[r] = scv[r];
    red4op(m4, true, red);
    float e4[4], s4[4];
    #pragma unroll
    for (int r = 0; r < 4; r++) { e4[r] = expf(scv[r] - m4[r]); s4[r] = e4[r]; }
    red4op(s4, false, red);

    float wrn[4];
    #pragma unroll
    for (int r = 0; r < 4; r++) {
        float bwd = 0.f;
        #pragma unroll 8
        for (int ch = 0; ch < NCH; ch++)
            bwd += g_bwdP[((b * NCH + ch) * 4 + r) * NN + tid];
        float fw = g_fwd[(b * 4 + r) * NN + tid];
        float cr = e4[r] / s4[r];
        wrn[r] = mbv[r] * bwd + mfv[r] * fw + mcv[r] * cr;
    }
    #pragma unroll
    for (int r = 0; r < 4; r++) {
        wr_s[r][tid] = wrn[r];
        g_wr[(b * RR + r) * NN + tid] = wrn[r];
    }
    __syncthreads();

    // read words -> combined activation buffer (rw cols [0,256)) + rwall
    {
        int r = tid >> 6, w = tid & 63;
        float acc = 0.f;
        for (int n2 = 0; n2 < NN; n2++)
            acc += wr_s[r][n2] * g_M[((size_t)(b * NN) + n2) * WWD + w];
        g_act[par ^ 1][b * RLEN + r * 64 + w] = acc;
        g_rwall[((size_t)t * BB + b) * (RR * WWD) + r * WWD + w] = acc;
    }
}

// -------------------- K6: batched output GEMM (verbatim) --------------------
__global__ void k_out(const float* __restrict__ Wout,
                      const float* __restrict__ bout,
                      float* __restrict__ out) {
    __shared__ float As[32][33];
    __shared__ float Bs[32][33];
    int tx = threadIdx.x & 15, ty = threadIdx.x >> 4;
    int tb0 = blockIdx.x * 32, o0 = blockIdx.y * 32;
    float acc00 = 0.f, acc01 = 0.f, acc10 = 0.f, acc11 = 0.f;
    for (int kt = 0; kt < 768; kt += 32) {
        for (int l = threadIdx.x; l < 1024; l += 256) {
            int mi = l >> 5, ki = l & 31;
            int k = kt + ki;
            int tb = tb0 + mi;
            float av = (k < 512) ? g_hall[(size_t)tb * HH + k]
                                 : g_rwall[(size_t)tb * (RR * WWD) + (k - 512)];
            As[mi][ki] = av;
            Bs[mi][ki] = Wout[(size_t)(o0 + mi) * 768 + k];
        }
        __syncthreads();
        #pragma unroll 8
        for (int ki = 0; ki < 32; ki++) {
            float a0 = As[ty * 2][ki], a1 = As[ty * 2 + 1][ki];
            float b0 = Bs[tx * 2][ki], b1 = Bs[tx * 2 + 1][ki];
            acc00 += a0 * b0; acc01 += a0 * b1;
            acc10 += a1 * b0; acc11 += a1 * b1;
        }
        __syncthreads();
    }
    int tb = tb0 + ty * 2, o = o0 + tx * 2;
    float bo0 = bout[o], bo1 = bout[o + 1];
    out[(size_t)tb * OUTD + o] = acc00 + bo0;
    out[(size_t)tb * OUTD + o + 1] = acc01 + bo1;
    out[(size_t)(tb + 1) * OUTD + o] = acc10 + bo0;
    out[(size_t)(tb + 1) * OUTD + o + 1] = acc11 + bo1;
}

// -------------------- host launch --------------------
extern "C" void kernel_launch(void* const* d_in, const int* in_sizes, int n_in,
                              void* d_out, int out_size) {
    const float* x    = (const float*)d_in[0];
    const float* Wih  = (const float*)d_in[1];
    const float* Whh  = (const float*)d_in[2];
    const float* bih  = (const float*)d_in[3];
    const float* bhh  = (const float*)d_in[4];
    const float* Wint = (const float*)d_in[5];
    const float* bint = (const float*)d_in[6];
    const float* Wout = (const float*)d_in[7];
    const float* bout = (const float*)d_in[8];
    float* out = (float*)d_out;

    void* p;
    cudaGetSymbolAddress(&p, g_act);   cudaMemsetAsync(p, 0, sizeof(float) * 2 * BB * RLEN);
    cudaGetSymbolAddress(&p, g_c);     cudaMemsetAsync(p, 0, sizeof(float) * BB * HH);
    cudaGetSymbolAddress(&p, g_M);     cudaMemsetAsync(p, 0, sizeof(float) * BB * NN * WWD);
    cudaGetSymbolAddress(&p, g_usage); cudaMemsetAsync(p, 0, sizeof(float) * BB * NN);
    cudaGetSymbolAddress(&p, g_link);  cudaMemsetAsync(p, 0, sizeof(float) * BB * NN * NN);
    cudaGetSymbolAddress(&p, g_prec);  cudaMemsetAsync(p, 0, sizeof(float) * 2 * BB * NN);
    cudaGetSymbolAddress(&p, g_wr);    cudaMemsetAsync(p, 0, sizeof(float) * BB * RR * NN);
    cudaGetSymbolAddress(&p, g_ww);    cudaMemsetAsync(p, 0, sizeof(float) * BB * NN);

    k_transpose<<<(ITFD * HH + 255) / 256, 256>>>(Wint);
    k_prep_wrec<<<(G4H * RLEN + 255) / 256, 256>>>(Wih, Whh);
    k_gatesx<<<dim3(32, 64), 256>>>(x, Wih, bih, bhh);

    for (int t = 0; t < TT; t++) {
        int par = t & 1;
        k_lstm<<<dim3(512, 2), 256>>>(t, par);
        k_itf2<<<118, 256>>>(bint, par);
        k_write<<<16, 256>>>(par);
        k_mem2<<<512, 256>>>(par);
        k_read2<<<16, 256>>>(t, par);
    }
    k_out<<<dim3(32, 8), 256>>>(Wout, bout, out);
}

// round 13
// speedup vs baseline: 1.1445x; 1.1445x over previous
#include <cuda_runtime.h>
#include <math.h>

#define BB    16
#define TT    64
#define IND   256
#define HH    512
#define NN    256
#define WWD   64
#define RR    4
#define OUTD  256
#define ITFD  471
#define G4H   2048   // 4*H
#define RLEN  768    // combined activation row: 256 (rw) + 512 (h)
#define NCH   16     // link row-chunks per batch (16 rows each)

// interface vector offsets
#define O_RK 0
#define O_RS 256
#define O_WK 260
#define O_WS 324
#define O_ER 325
#define O_WV 389
#define O_FG 453
#define O_AG 457
#define O_WG 458
#define O_MO 459
#define EPSF 1e-6f

// -------------------- persistent state --------------------
__device__ __align__(16) float g_act[2][BB * RLEN];   // [rw(256) | h(512)] per batch
__device__ __align__(16) float g_c[BB * HH];
__device__ __align__(16) float g_M[BB * NN * WWD];
__device__ __align__(16) float g_usage[BB * NN];
__device__ __align__(16) float g_link[BB * NN * NN];
__device__ __align__(16) float g_prec[2][BB * NN];
__device__ __align__(16) float g_wr[BB * RR * NN];
__device__ __align__(16) float g_ww[BB * NN];
__device__ __align__(16) float g_itf[BB * ITFD];
__device__ __align__(16) float g_hall[TT * BB * HH];
__device__ __align__(16) float g_rwall[TT * BB * RR * WWD];
__device__ __align__(16) float g_WintT[ITFD * HH];
__device__ __align__(16) float g_bwdP[BB * NCH * RR * NN];
__device__ __align__(16) float g_fwd[BB * RR * NN];
__device__ __align__(16) float g_Wrec[G4H * RLEN];       // [2048][768] = [W_ih(rw cols) | W_hh]
__device__ __align__(16) float g_gatesx[TT * BB * G4H];  // x-part of gates + biases

// -------------------- helpers --------------------
__device__ __forceinline__ float sigf(float x) { return 1.f / (1.f + expf(-x)); }
__device__ __forceinline__ float softplusf(float x) {
    return fmaxf(x, 0.f) + log1pf(expf(-fabsf(x)));
}
__device__ __forceinline__ float oneplusf(float x) { return 1.f + softplusf(x); }

__device__ __forceinline__ float blk_max256(float v, float* red, int tid) {
    red[tid] = v; __syncthreads();
    for (int s = 128; s > 0; s >>= 1) {
        if (tid < s) red[tid] = fmaxf(red[tid], red[tid + s]);
        __syncthreads();
    }
    float r = red[0]; __syncthreads();
    return r;
}
__device__ __forceinline__ float blk_sum256(float v, float* red, int tid) {
    red[tid] = v; __syncthreads();
    for (int s = 128; s > 0; s >>= 1) {
        if (tid < s) red[tid] = red[tid] + red[tid + s];
        __syncthreads();
    }
    float r = red[0]; __syncthreads();
    return r;
}

__device__ __forceinline__ void red4op(float v[4], bool domax, volatile float* red) {
    int tid = threadIdx.x;
    #pragma unroll
    for (int r = 0; r < 4; r++)
        #pragma unroll
        for (int o = 16; o; o >>= 1) {
            float u = __shfl_xor_sync(0xffffffffu, v[r], o);
            v[r] = domax ? fmaxf(v[r], u) : (v[r] + u);
        }
    if ((tid & 31) == 0) {
        int w = tid >> 5;
        red[w * 4 + 0] = v[0]; red[w * 4 + 1] = v[1];
        red[w * 4 + 2] = v[2]; red[w * 4 + 3] = v[3];
    }
    __syncthreads();
    if (tid == 0) {
        #pragma unroll
        for (int r = 0; r < 4; r++) {
            float a = red[r];
            for (int w = 1; w < 8; w++) {
                float u = red[w * 4 + r];
                a = domax ? fmaxf(a, u) : (a + u);
            }
            red[40 + r] = a;
        }
    }
    __syncthreads();
    v[0] = red[40]; v[1] = red[41]; v[2] = red[42]; v[3] = red[43];
    __syncthreads();
}

// -------------------- prep kernels (one-time) --------------------
__global__ void k_transpose(const float* __restrict__ Wint) {
    int idx = blockIdx.x * 256 + threadIdx.x;
    if (idx < ITFD * HH) {
        int c = idx / HH;
        int k = idx - c * HH;
        g_WintT[idx] = Wint[(size_t)k * ITFD + c];
    }
}

__global__ void k_prep_wrec(const float* __restrict__ Wih,
                            const float* __restrict__ Whh) {
    int idx = blockIdx.x * 256 + threadIdx.x;
    if (idx < G4H * RLEN) {
        int row = idx / RLEN;
        int c = idx - row * RLEN;
        g_Wrec[idx] = (c < 256) ? Wih[(size_t)row * 512 + 256 + c]
                                : Whh[(size_t)row * 512 + (c - 256)];
    }
}

__global__ void k_gatesx(const float* __restrict__ x,
                         const float* __restrict__ Wih,
                         const float* __restrict__ bih,
                         const float* __restrict__ bhh) {
    __shared__ float As[32][33];
    __shared__ float Bs[32][33];
    int tx = threadIdx.x & 15, ty = threadIdx.x >> 4;
    int m0 = blockIdx.x * 32, n0 = blockIdx.y * 32;
    float a00 = 0.f, a01 = 0.f, a10 = 0.f, a11 = 0.f;
    for (int kt = 0; kt < 256; kt += 32) {
        for (int l = threadIdx.x; l < 1024; l += 256) {
            int mi = l >> 5, ki = l & 31;
            As[mi][ki] = x[(size_t)(m0 + mi) * IND + kt + ki];
            Bs[mi][ki] = Wih[(size_t)(n0 + mi) * 512 + kt + ki];
        }
        __syncthreads();
        #pragma unroll 8
        for (int ki = 0; ki < 32; ki++) {
            float x0 = As[ty * 2][ki], x1 = As[ty * 2 + 1][ki];
            float w0 = Bs[tx * 2][ki], w1 = Bs[tx * 2 + 1][ki];
            a00 += x0 * w0; a01 += x0 * w1;
            a10 += x1 * w0; a11 += x1 * w1;
        }
        __syncthreads();
    }
    int m = m0 + ty * 2, n = n0 + tx * 2;
    float c0 = bih[n] + bhh[n], c1 = bih[n + 1] + bhh[n + 1];
    g_gatesx[(size_t)m * G4H + n] = a00 + c0;
    g_gatesx[(size_t)m * G4H + n + 1] = a01 + c1;
    g_gatesx[(size_t)(m + 1) * G4H + n] = a10 + c0;
    g_gatesx[(size_t)(m + 1) * G4H + n + 1] = a11 + c1;
}

// -------------------- K1: LSTM recurrent, grid 512, smem-staged act -------------
// One j per block; all 16 batches staged in smem (coalesced); weights read once.
// tid = kc*16 + b; kc covers 48 contiguous cols.
__global__ void __launch_bounds__(256) k_lstm(int t, int par) {
    __shared__ float sAct[16][772];    // stride 772 -> conflict-free float4 LDS
    __shared__ float sgate[4][8][16];
    __shared__ float gfin[4][16];
    int tid = threadIdx.x;
    int j  = blockIdx.x;

    // stage 16 batches x 768 cols, coalesced (3072 float4, 12 per thread)
    for (int i = tid; i < 3072; i += 256) {
        int b = i / 192, q = i - (i / 192) * 192;
        float4 v = ((const float4*)(g_act[par] + (size_t)b * RLEN))[q];
        *(float4*)&sAct[b][q * 4] = v;
    }
    __syncthreads();

    int kc = tid >> 4;      // 0..15
    int b  = tid & 15;
    int c0 = kc * 48;

    const float4* a4  = (const float4*)&sAct[b][c0];
    const float4* w04 = (const float4*)(g_Wrec + (size_t)(0 * HH + j) * RLEN + c0);
    const float4* w14 = (const float4*)(g_Wrec + (size_t)(1 * HH + j) * RLEN + c0);
    const float4* w24 = (const float4*)(g_Wrec + (size_t)(2 * HH + j) * RLEN + c0);
    const float4* w34 = (const float4*)(g_Wrec + (size_t)(3 * HH + j) * RLEN + c0);

    float acc0 = 0.f, acc1 = 0.f, acc2 = 0.f, acc3 = 0.f;
    #pragma unroll
    for (int q = 0; q < 12; q++) {
        float4 av = a4[q];
        float4 wv;
        wv = w04[q]; acc0 += av.x * wv.x + av.y * wv.y + av.z * wv.z + av.w * wv.w;
        wv = w14[q]; acc1 += av.x * wv.x + av.y * wv.y + av.z * wv.z + av.w * wv.w;
        wv = w24[q]; acc2 += av.x * wv.x + av.y * wv.y + av.z * wv.z + av.w * wv.w;
        wv = w34[q]; acc3 += av.x * wv.x + av.y * wv.y + av.z * wv.z + av.w * wv.w;
    }
    // combine kc pairs within warp (lanes 16 apart share (kc, kc^1))
    acc0 += __shfl_xor_sync(0xffffffffu, acc0, 16);
    acc1 += __shfl_xor_sync(0xffffffffu, acc1, 16);
    acc2 += __shfl_xor_sync(0xffffffffu, acc2, 16);
    acc3 += __shfl_xor_sync(0xffffffffu, acc3, 16);
    int w = tid >> 5;
    if ((tid & 16) == 0) {
        sgate[0][w][b] = acc0; sgate[1][w][b] = acc1;
        sgate[2][w][b] = acc2; sgate[3][w][b] = acc3;
    }
    __syncthreads();
    if (tid < 64) {
        int g = tid >> 4, bb = tid & 15;
        float s = 0.f;
        #pragma unroll
        for (int w2 = 0; w2 < 8; w2++) s += sgate[g][w2][bb];
        gfin[g][bb] = s;
    }
    __syncthreads();
    if (tid < 16) {
        int bb = tid;
        const float* gx = g_gatesx + ((size_t)t * BB + bb) * G4H;
        float gi = gfin[0][bb] + gx[0 * HH + j];
        float gf = gfin[1][bb] + gx[1 * HH + j];
        float gg = gfin[2][bb] + gx[2 * HH + j];
        float go = gfin[3][bb] + gx[3 * HH + j];
        float cold = g_c[bb * HH + j];
        float cn = sigf(gf) * cold + sigf(gi) * tanhf(gg);
        float hn = sigf(go) * tanhf(cn);
        g_c[bb * HH + j] = cn;
        g_act[par ^ 1][bb * RLEN + 256 + j] = hn;
        g_hall[((size_t)t * BB + bb) * HH + j] = hn;
    }
}

// -------------------- K2: wide interface GEMV (grid 118, block 256) -------------
__global__ void __launch_bounds__(256) k_itf2(const float* __restrict__ bint, int par) {
    __shared__ float hS[16 * 512];
    int tid = threadIdx.x;
    for (int i = tid; i < 2048; i += 256) {      // 2048 float4
        int b = i >> 7, q = i & 127;
        ((float4*)hS)[i] = ((const float4*)(g_act[par ^ 1] + b * RLEN + 256))[q];
    }
    __syncthreads();

    int lane = tid & 31, w = tid >> 5;
    int cbase = blockIdx.x * 4;
    #pragma unroll
    for (int i = 0; i < 8; i++) {
        int task = i * 8 + w;
        int c = cbase + (task >> 4);
        int b = task & 15;
        if (c < ITFD) {
            const float4* w4 = (const float4*)(g_WintT + (size_t)c * HH);
            const float4* h4 = (const float4*)(hS + b * 512);
            float acc = 0.f;
            #pragma unroll
            for (int q = 0; q < 4; q++) {
                float4 wv = w4[lane + q * 32];
                float4 hv = h4[lane + q * 32];
                acc += wv.x * hv.x + wv.y * hv.y + wv.z * hv.z + wv.w * hv.w;
            }
            #pragma unroll
            for (int o = 16; o; o >>= 1) acc += __shfl_xor_sync(0xffffffffu, acc, o);
            if (lane == 0) g_itf[b * ITFD + c] = acc + bint[c];
        }
    }
}

// -------------------- K3: per-batch write addressing (grid 16) ------------------
__global__ void __launch_bounds__(256) k_write(int par) {
    int b = blockIdx.x;
    int tid = threadIdx.x;
    __shared__ float itfs[ITFD + 1];
    __shared__ float uval[NN];
    __shared__ int   uidx[NN];
    __shared__ float allocv[NN];
    __shared__ float red[NN];
    __shared__ float karr[WWD];
    __shared__ float sc_knorm, sc_beta;

    for (int i = tid; i < ITFD; i += 256) itfs[i] = g_itf[b * ITFD + i];
    __syncthreads();

    float fg0 = sigf(itfs[O_FG + 0]);
    float fg1 = sigf(itfs[O_FG + 1]);
    float fg2 = sigf(itfs[O_FG + 2]);
    float fg3 = sigf(itfs[O_FG + 3]);
    float ag  = sigf(itfs[O_AG]);
    float wg  = sigf(itfs[O_WG]);

    int n = tid;
    float psi = 1.f;
    psi *= (1.f - fg0 * g_wr[(b * RR + 0) * NN + n]);
    psi *= (1.f - fg1 * g_wr[(b * RR + 1) * NN + n]);
    psi *= (1.f - fg2 * g_wr[(b * RR + 2) * NN + n]);
    psi *= (1.f - fg3 * g_wr[(b * RR + 3) * NN + n]);
    float u = g_usage[b * NN + n];
    float wagg = g_ww[b * NN + n];  // NW=1
    float un = (u + wagg - u * wagg) * psi;
    g_usage[b * NN + n] = un;

    if (tid < WWD) karr[tid] = itfs[O_WK + tid];
    __syncthreads();
    if (tid == 0) {
        float ss = 0.f;
        for (int w = 0; w < WWD; w++) ss += karr[w] * karr[w];
        sc_knorm = sqrtf(ss) + EPSF;
        sc_beta  = oneplusf(itfs[O_WS]);
    }
    __syncthreads();

    float dot = 0.f, ss = 0.f;
    const float* Mrow = g_M + ((size_t)(b * NN) + n) * WWD;
    #pragma unroll 8
    for (int w = 0; w < WWD; w++) {
        float m = Mrow[w];
        dot += m * karr[w];
        ss += m * m;
    }
    float sim = (dot / sc_knorm) / (sqrtf(ss) + EPSF);
    float sco = sc_beta * sim;
    float mx = blk_max256(sco, red, tid);
    float e = expf(sco - mx);
    float sm = blk_sum256(e, red, tid);
    float cwv = e / sm;

    // stable bitonic sort ascending on (usage, index); shfl for jmp<32
    float v = un; int ix = tid;
    for (int k2 = 2; k2 <= NN; k2 <<= 1) {
        for (int jmp = k2 >> 1; jmp; jmp >>= 1) {
            bool up = ((tid & k2) == 0);
            float v2; int i2;
            if (jmp >= 32) {
                uval[tid] = v; uidx[tid] = ix;
                __syncthreads();
                v2 = uval[tid ^ jmp]; i2 = uidx[tid ^ jmp];
                __syncthreads();
            } else {
                v2 = __shfl_xor_sync(0xffffffffu, v, jmp);
                i2 = __shfl_xor_sync(0xffffffffu, ix, jmp);
            }
            bool lower = ((tid & jmp) == 0);
            bool iless = (v < v2) || (v == v2 && ix < i2);
            bool keep = (iless == (lower == up));
            if (!keep) { v = v2; ix = i2; }
        }
    }

    // exclusive product scan over sorted usage -> allocation
    {
        int lane = tid & 31, wid = tid >> 5;
        float p = v;
        #pragma unroll
        for (int o = 1; o < 32; o <<= 1) {
            float q = __shfl_up_sync(0xffffffffu, p, o);
            if (lane >= o) p *= q;
        }
        if (lane == 31) red[wid] = p;
        __syncthreads();
        if (tid == 0) {
            float a = 1.f;
            #pragma unroll
            for (int w = 0; w < 8; w++) { float q = red[w]; red[8 + w] = a; a *= q; }
        }
        __syncthreads();
        float tmp = __shfl_up_sync(0xffffffffu, p, 1);
        float exclw = (lane == 0) ? 1.f : tmp;
        float excl = red[8 + wid] * exclw;
        allocv[ix] = (1.f - v) * excl;
        __syncthreads();
    }

    float wwn = wg * (ag * allocv[tid] + (1.f - ag) * cwv);
    g_ww[b * NN + tid] = wwn;
    float wsum = blk_sum256(wwn, red, tid);
    float pold = g_prec[par][b * NN + tid];
    g_prec[par ^ 1][b * NN + tid] = (1.f - wsum) * pold + wwn;
}

// -------------------- K4: wide link+M update (grid 256 = 16b x 16ch, R9) --------
__global__ void __launch_bounds__(256) k_mem2(int par) {
    int blk = blockIdx.x;
    int b = blk >> 4, ch = blk & 15;
    int tid = threadIdx.x;
    __shared__ float sww[NN];
    __shared__ float sprec[NN];
    __shared__ float wr4[4][NN];
    __shared__ float er[WWD];
    __shared__ float vv[WWD];
    __shared__ float tile[16][260];

    sww[tid]   = g_ww[b * NN + tid];
    sprec[tid] = g_prec[par][b * NN + tid];
    #pragma unroll
    for (int r = 0; r < RR; r++) wr4[r][tid] = g_wr[(b * RR + r) * NN + tid];
    if (tid < WWD) {
        er[tid] = sigf(g_itf[b * ITFD + O_ER + tid]);
        vv[tid] = sigf(g_itf[b * ITFD + O_WV + tid]);
    }
    __syncthreads();

    float wwj = sww[tid];
    float prj = sprec[tid];
    float bp0 = 0.f, bp1 = 0.f, bp2 = 0.f, bp3 = 0.f;
    float* lbase = g_link + (size_t)b * (NN * NN);
    #pragma unroll 4
    for (int ii = 0; ii < 16; ii++) {
        int i = ch * 16 + ii;
        float wwi = sww[i];
        float l = lbase[(size_t)i * NN + tid];
        float nv = (1.f - wwi - wwj) * l + wwi * prj;
        if (i == tid) nv = 0.f;
        lbase[(size_t)i * NN + tid] = nv;
        tile[ii][tid] = nv;
        bp0 += nv * wr4[0][i];
        bp1 += nv * wr4[1][i];
        bp2 += nv * wr4[2][i];
        bp3 += nv * wr4[3][i];
    }
    g_bwdP[((b * NCH + ch) * 4 + 0) * NN + tid] = bp0;
    g_bwdP[((b * NCH + ch) * 4 + 1) * NN + tid] = bp1;
    g_bwdP[((b * NCH + ch) * 4 + 2) * NN + tid] = bp2;
    g_bwdP[((b * NCH + ch) * 4 + 3) * NN + tid] = bp3;
    __syncthreads();

    {
        int warp = tid >> 5, lane = tid & 31;
        #pragma unroll
        for (int q = 0; q < 2; q++) {
            int ii = warp * 2 + q;
            int i = ch * 16 + ii;
            float a0 = 0.f, a1 = 0.f, a2 = 0.f, a3 = 0.f;
            #pragma unroll
            for (int p = 0; p < 8; p++) {
                int jx = lane + p * 32;
                float lv = tile[ii][jx];
                a0 += lv * wr4[0][jx]; a1 += lv * wr4[1][jx];
                a2 += lv * wr4[2][jx]; a3 += lv * wr4[3][jx];
            }
            #pragma unroll
            for (int o = 16; o; o >>= 1) {
                a0 += __shfl_down_sync(0xffffffffu, a0, o);
                a1 += __shfl_down_sync(0xffffffffu, a1, o);
                a2 += __shfl_down_sync(0xffffffffu, a2, o);
                a3 += __shfl_down_sync(0xffffffffu, a3, o);
            }
            if (lane == 0) {
                g_fwd[(b * 4 + 0) * NN + i] = a0;
                g_fwd[(b * 4 + 1) * NN + i] = a1;
                g_fwd[(b * 4 + 2) * NN + i] = a2;
                g_fwd[(b * 4 + 3) * NN + i] = a3;
            }
        }
    }

    {
        int n = ch * 16 + (tid >> 4);
        int w0 = (tid & 15) * 4;
        float wwn = sww[n];
        float* Mp = g_M + ((size_t)(b * NN) + n) * WWD + w0;
        #pragma unroll
        for (int q = 0; q < 4; q++)
            Mp[q] = Mp[q] * (1.f - wwn * er[w0 + q]) + wwn * vv[w0 + q];
    }
}

// -------------------- K5: per-batch read combine (grid 16) ----------------------
__global__ void __launch_bounds__(256) k_read2(int t, int par) {
    int b = blockIdx.x;
    int tid = threadIdx.x;
    __shared__ float kn[RR][WWD];
    __shared__ float wr_s[RR][NN];
    __shared__ float red[64];
    __shared__ float betas[RR], knorm[RR], mbv[RR], mfv[RR], mcv[RR];

    const float* itf = g_itf + (size_t)b * ITFD;

    {
        int r = tid >> 6, w = tid & 63;
        kn[r][w] = itf[O_RK + r * WWD + w];
    }
    __syncthreads();
    if (tid < RR) {
        float ss2 = 0.f;
        for (int w = 0; w < WWD; w++) ss2 += kn[tid][w] * kn[tid][w];
        knorm[tid] = sqrtf(ss2) + EPSF;
        betas[tid] = oneplusf(itf[O_RS + tid]);
        float m0 = itf[O_MO + tid * 3 + 0];
        float m1 = itf[O_MO + tid * 3 + 1];
        float m2 = itf[O_MO + tid * 3 + 2];
        float mxm = fmaxf(m0, fmaxf(m1, m2));
        float e0 = expf(m0 - mxm), e1 = expf(m1 - mxm), e2 = expf(m2 - mxm);
        float s = e0 + e1 + e2;
        mbv[tid] = e0 / s; mfv[tid] = e1 / s; mcv[tid] = e2 / s;
    }
    __syncthreads();

    const float* Mrow = g_M + ((size_t)(b * NN) + tid) * WWD;
    float d0 = 0.f, d1 = 0.f, d2 = 0.f, d3 = 0.f, ss2 = 0.f;
    #pragma unroll 8
    for (int w = 0; w < WWD; w++) {
        float m = Mrow[w];
        ss2 += m * m;
        d0 += m * kn[0][w]; d1 += m * kn[1][w]; d2 += m * kn[2][w]; d3 += m * kn[3][w];
    }
    float inv = 1.f / (sqrtf(ss2) + EPSF);
    float scv[4], m4[4];
    scv[0] = betas[0] * (d0 / knorm[0]) * inv;
    scv[1] = betas[1] * (d1 / knorm[1]) * inv;
    scv[2] = betas[2] * (d2 / knorm[2]) * inv;
    scv[3] = betas[3] * (d3 / knorm[3]) * inv;
    #pragma unroll
    for (int r = 0; r < 4; r++) m4[r] = scv[r];
    red4op(m4, true, red);
    float e4[4], s4[4];
    #pragma unroll
    for (int r = 0; r < 4; r++) { e4[r] = expf(scv[r] - m4[r]); s4[r] = e4[r]; }
    red4op(s4, false, red);

    float wrn[4];
    #pragma unroll
    for (int r = 0; r < 4; r++) {
        float bwd = 0.f;
        #pragma unroll
        for (int ch = 0; ch < NCH; ch++)
            bwd += g_bwdP[((b * NCH + ch) * 4 + r) * NN + tid];
        float fw = g_fwd[(b * 4 + r) * NN + tid];
        float cr = e4[r] / s4[r];
        wrn[r] = mbv[r] * bwd + mfv[r] * fw + mcv[r] * cr;
    }
    #pragma unroll
    for (int r = 0; r < 4; r++) {
        wr_s[r][tid] = wrn[r];
        g_wr[(b * RR + r) * NN + tid] = wrn[r];
    }
    __syncthreads();

    // read words -> combined activation buffer (rw cols [0,256)) + rwall
    {
        int r = tid >> 6, w = tid & 63;
        float acc = 0.f;
        for (int n2 = 0; n2 < NN; n2++)
            acc += wr_s[r][n2] * g_M[((size_t)(b * NN) + n2) * WWD + w];
        g_act[par ^ 1][b * RLEN + r * 64 + w] = acc;
        g_rwall[((size_t)t * BB + b) * (RR * WWD) + r * WWD + w] = acc;
    }
}

// -------------------- K6: batched output GEMM (verbatim) --------------------
__global__ void k_out(const float* __restrict__ Wout,
                      const float* __restrict__ bout,
                      float* __restrict__ out) {
    __shared__ float As[32][33];
    __shared__ float Bs[32][33];
    int tx = threadIdx.x & 15, ty = threadIdx.x >> 4;
    int tb0 = blockIdx.x * 32, o0 = blockIdx.y * 32;
    float acc00 = 0.f, acc01 = 0.f, acc10 = 0.f, acc11 = 0.f;
    for (int kt = 0; kt < 768; kt += 32) {
        for (int l = threadIdx.x; l < 1024; l += 256) {
            int mi = l >> 5, ki = l & 31;
            int k = kt + ki;
            int tb = tb0 + mi;
            float av = (k < 512) ? g_hall[(size_t)tb * HH + k]
                                 : g_rwall[(size_t)tb * (RR * WWD) + (k - 512)];
            As[mi][ki] = av;
            Bs[mi][ki] = Wout[(size_t)(o0 + mi) * 768 + k];
        }
        __syncthreads();
        #pragma unroll 8
        for (int ki = 0; ki < 32; ki++) {
            float a0 = As[ty * 2][ki], a1 = As[ty * 2 + 1][ki];
            float b0 = Bs[tx * 2][ki], b1 = Bs[tx * 2 + 1][ki];
            acc00 += a0 * b0; acc01 += a0 * b1;
            acc10 += a1 * b0; acc11 += a1 * b1;
        }
        __syncthreads();
    }
    int tb = tb0 + ty * 2, o = o0 + tx * 2;
    float bo0 = bout[o], bo1 = bout[o + 1];
    out[(size_t)tb * OUTD + o] = acc00 + bo0;
    out[(size_t)tb * OUTD + o + 1] = acc01 + bo1;
    out[(size_t)(tb + 1) * OUTD + o] = acc10 + bo0;
    out[(size_t)(tb + 1) * OUTD + o + 1] = acc11 + bo1;
}

// -------------------- host launch --------------------
extern "C" void kernel_launch(void* const* d_in, const int* in_sizes, int n_in,
                              void* d_out, int out_size) {
    const float* x    = (const float*)d_in[0];
    const float* Wih  = (const float*)d_in[1];
    const float* Whh  = (const float*)d_in[2];
    const float* bih  = (const float*)d_in[3];
    const float* bhh  = (const float*)d_in[4];
    const float* Wint = (const float*)d_in[5];
    const float* bint = (const float*)d_in[6];
    const float* Wout = (const float*)d_in[7];
    const float* bout = (const float*)d_in[8];
    float* out = (float*)d_out;

    void* p;
    cudaGetSymbolAddress(&p, g_act);   cudaMemsetAsync(p, 0, sizeof(float) * 2 * BB * RLEN);
    cudaGetSymbolAddress(&p, g_c);     cudaMemsetAsync(p, 0, sizeof(float) * BB * HH);
    cudaGetSymbolAddress(&p, g_M);     cudaMemsetAsync(p, 0, sizeof(float) * BB * NN * WWD);
    cudaGetSymbolAddress(&p, g_usage); cudaMemsetAsync(p, 0, sizeof(float) * BB * NN);
    cudaGetSymbolAddress(&p, g_link);  cudaMemsetAsync(p, 0, sizeof(float) * BB * NN * NN);
    cudaGetSymbolAddress(&p, g_prec);  cudaMemsetAsync(p, 0, sizeof(float) * 2 * BB * NN);
    cudaGetSymbolAddress(&p, g_wr);    cudaMemsetAsync(p, 0, sizeof(float) * BB * RR * NN);
    cudaGetSymbolAddress(&p, g_ww);    cudaMemsetAsync(p, 0, sizeof(float) * BB * NN);

    k_transpose<<<(ITFD * HH + 255) / 256, 256>>>(Wint);
    k_prep_wrec<<<(G4H * RLEN + 255) / 256, 256>>>(Wih, Whh);
    k_gatesx<<<dim3(32, 64), 256>>>(x, Wih, bih, bhh);

    for (int t = 0; t < TT; t++) {
        int par = t & 1;
        k_lstm<<<512, 256>>>(t, par);
        k_itf2<<<118, 256>>>(bint, par);
        k_write<<<16, 256>>>(par);
        k_mem2<<<256, 256>>>(par);
        k_read2<<<16, 256>>>(t, par);
    }
    k_out<<<dim3(32, 8), 256>>>(Wout, bout, out);
}

// round 14
// speedup vs baseline: 1.2660x; 1.1061x over previous
#include <cuda_runtime.h>
#include <math.h>

#define BB    16
#define TT    64
#define IND   256
#define HH    512
#define NN    256
#define WWD   64
#define RR    4
#define OUTD  256
#define ITFD  471
#define G4H   2048   // 4*H
#define RLEN  768    // combined activation row: 256 (rw) + 512 (h)
#define NCH   16     // link row-chunks per batch (16 rows each)

// interface vector offsets
#define O_RK 0
#define O_RS 256
#define O_WK 260
#define O_WS 324
#define O_ER 325
#define O_WV 389
#define O_FG 453
#define O_AG 457
#define O_WG 458
#define O_MO 459
#define EPSF 1e-6f

// -------------------- persistent state --------------------
__device__ __align__(16) float g_act[2][BB * RLEN];   // [rw(256) | h(512)] per batch
__device__ __align__(16) float g_c[BB * HH];
__device__ __align__(16) float g_M[BB * NN * WWD];
__device__ __align__(16) float g_usage[BB * NN];
__device__ __align__(16) float g_link[BB * NN * NN];
__device__ __align__(16) float g_prec[2][BB * NN];
__device__ __align__(16) float g_wr[BB * RR * NN];
__device__ __align__(16) float g_ww[BB * NN];
__device__ __align__(16) float g_itf[BB * ITFD];
__device__ __align__(16) float g_hall[TT * BB * HH];
__device__ __align__(16) float g_rwall[TT * BB * RR * WWD];
__device__ __align__(16) float g_WintT[ITFD * HH];
__device__ __align__(16) float g_bwdP[BB * NCH * RR * NN];
__device__ __align__(16) float g_fwd[BB * RR * NN];
__device__ __align__(16) float g_Wrec[G4H * RLEN];       // [2048][768] = [W_ih(rw cols) | W_hh]
__device__ __align__(16) float g_gatesx[TT * BB * G4H];  // x-part of gates + biases

// -------------------- helpers --------------------
__device__ __forceinline__ float sigf(float x) { return 1.f / (1.f + expf(-x)); }
__device__ __forceinline__ float softplusf(float x) {
    return fmaxf(x, 0.f) + log1pf(expf(-fabsf(x)));
}
__device__ __forceinline__ float oneplusf(float x) { return 1.f + softplusf(x); }

__device__ __forceinline__ float blk_max256(float v, float* red, int tid) {
    red[tid] = v; __syncthreads();
    for (int s = 128; s > 0; s >>= 1) {
        if (tid < s) red[tid] = fmaxf(red[tid], red[tid + s]);
        __syncthreads();
    }
    float r = red[0]; __syncthreads();
    return r;
}
__device__ __forceinline__ float blk_sum256(float v, float* red, int tid) {
    red[tid] = v; __syncthreads();
    for (int s = 128; s > 0; s >>= 1) {
        if (tid < s) red[tid] = red[tid] + red[tid + s];
        __syncthreads();
    }
    float r = red[0]; __syncthreads();
    return r;
}

__device__ __forceinline__ void red4op(float v[4], bool domax, volatile float* red) {
    int tid = threadIdx.x;
    #pragma unroll
    for (int r = 0; r < 4; r++)
        #pragma unroll
        for (int o = 16; o; o >>= 1) {
            float u = __shfl_xor_sync(0xffffffffu, v[r], o);
            v[r] = domax ? fmaxf(v[r], u) : (v[r] + u);
        }
    if ((tid & 31) == 0) {
        int w = tid >> 5;
        red[w * 4 + 0] = v[0]; red[w * 4 + 1] = v[1];
        red[w * 4 + 2] = v[2]; red[w * 4 + 3] = v[3];
    }
    __syncthreads();
    if (tid == 0) {
        #pragma unroll
        for (int r = 0; r < 4; r++) {
            float a = red[r];
            for (int w = 1; w < 8; w++) {
                float u = red[w * 4 + r];
                a = domax ? fmaxf(a, u) : (a + u);
            }
            red[40 + r] = a;
        }
    }
    __syncthreads();
    v[0] = red[40]; v[1] = red[41]; v[2] = red[42]; v[3] = red[43];
    __syncthreads();
}

// -------------------- prep kernels (one-time) --------------------
__global__ void k_transpose(const float* __restrict__ Wint) {
    int idx = blockIdx.x * 256 + threadIdx.x;
    if (idx < ITFD * HH) {
        int c = idx / HH;
        int k = idx - c * HH;
        g_WintT[idx] = Wint[(size_t)k * ITFD + c];
    }
}

__global__ void k_prep_wrec(const float* __restrict__ Wih,
                            const float* __restrict__ Whh) {
    int idx = blockIdx.x * 256 + threadIdx.x;
    if (idx < G4H * RLEN) {
        int row = idx / RLEN;
        int c = idx - row * RLEN;
        g_Wrec[idx] = (c < 256) ? Wih[(size_t)row * 512 + 256 + c]
                                : Whh[(size_t)row * 512 + (c - 256)];
    }
}

__global__ void k_gatesx(const float* __restrict__ x,
                         const float* __restrict__ Wih,
                         const float* __restrict__ bih,
                         const float* __restrict__ bhh) {
    __shared__ float As[32][33];
    __shared__ float Bs[32][33];
    int tx = threadIdx.x & 15, ty = threadIdx.x >> 4;
    int m0 = blockIdx.x * 32, n0 = blockIdx.y * 32;
    float a00 = 0.f, a01 = 0.f, a10 = 0.f, a11 = 0.f;
    for (int kt = 0; kt < 256; kt += 32) {
        for (int l = threadIdx.x; l < 1024; l += 256) {
            int mi = l >> 5, ki = l & 31;
            As[mi][ki] = x[(size_t)(m0 + mi) * IND + kt + ki];
            Bs[mi][ki] = Wih[(size_t)(n0 + mi) * 512 + kt + ki];
        }
        __syncthreads();
        #pragma unroll 8
        for (int ki = 0; ki < 32; ki++) {
            float x0 = As[ty * 2][ki], x1 = As[ty * 2 + 1][ki];
            float w0 = Bs[tx * 2][ki], w1 = Bs[tx * 2 + 1][ki];
            a00 += x0 * w0; a01 += x0 * w1;
            a10 += x1 * w0; a11 += x1 * w1;
        }
        __syncthreads();
    }
    int m = m0 + ty * 2, n = n0 + tx * 2;
    float c0 = bih[n] + bhh[n], c1 = bih[n + 1] + bhh[n + 1];
    g_gatesx[(size_t)m * G4H + n] = a00 + c0;
    g_gatesx[(size_t)m * G4H + n + 1] = a01 + c1;
    g_gatesx[(size_t)(m + 1) * G4H + n] = a10 + c0;
    g_gatesx[(size_t)(m + 1) * G4H + n + 1] = a11 + c1;
}

// -------------------- K1: LSTM recurrent, warp = 2 batches x 4 gates ------------
// grid 512 (one j per block), block 256 = 8 warps -> 16 batches.
// lane strides columns: col = p*128 + lane*4 (float4) -> 512B/warp-instr (4 lines).
// Pure intra-warp butterfly reduction; no smem, no __syncthreads.
__global__ void __launch_bounds__(256) k_lstm(int t, int par) {
    int tid = threadIdx.x;
    int lane = tid & 31;
    int w = tid >> 5;           // warp -> batches 2w, 2w+1
    int j = blockIdx.x;
    int b0 = w * 2;

    const float4* a0 = (const float4*)(g_act[par] + (size_t)b0 * RLEN);
    const float4* a1 = (const float4*)(g_act[par] + (size_t)(b0 + 1) * RLEN);
    const float4* w0 = (const float4*)(g_Wrec + (size_t)(0 * HH + j) * RLEN);
    const float4* w1 = (const float4*)(g_Wrec + (size_t)(1 * HH + j) * RLEN);
    const float4* w2 = (const float4*)(g_Wrec + (size_t)(2 * HH + j) * RLEN);
    const float4* w3 = (const float4*)(g_Wrec + (size_t)(3 * HH + j) * RLEN);

    float acc[4][2] = {{0.f, 0.f}, {0.f, 0.f}, {0.f, 0.f}, {0.f, 0.f}};
    #pragma unroll
    for (int p = 0; p < 6; p++) {
        int idx = p * 32 + lane;
        float4 av0 = a0[idx];
        float4 av1 = a1[idx];
        float4 wv;
        wv = w0[idx];
        acc[0][0] += wv.x * av0.x + wv.y * av0.y + wv.z * av0.z + wv.w * av0.w;
        acc[0][1] += wv.x * av1.x + wv.y * av1.y + wv.z * av1.z + wv.w * av1.w;
        wv = w1[idx];
        acc[1][0] += wv.x * av0.x + wv.y * av0.y + wv.z * av0.z + wv.w * av0.w;
        acc[1][1] += wv.x * av1.x + wv.y * av1.y + wv.z * av1.z + wv.w * av1.w;
        wv = w2[idx];
        acc[2][0] += wv.x * av0.x + wv.y * av0.y + wv.z * av0.z + wv.w * av0.w;
        acc[2][1] += wv.x * av1.x + wv.y * av1.y + wv.z * av1.z + wv.w * av1.w;
        wv = w3[idx];
        acc[3][0] += wv.x * av0.x + wv.y * av0.y + wv.z * av0.z + wv.w * av0.w;
        acc[3][1] += wv.x * av1.x + wv.y * av1.y + wv.z * av1.z + wv.w * av1.w;
    }
    // butterfly reduce all 8 accumulators across the warp
    #pragma unroll
    for (int o = 16; o; o >>= 1) {
        #pragma unroll
        for (int g = 0; g < 4; g++) {
            acc[g][0] += __shfl_xor_sync(0xffffffffu, acc[g][0], o);
            acc[g][1] += __shfl_xor_sync(0xffffffffu, acc[g][1], o);
        }
    }
    if (lane < 2) {
        int bb = b0 + lane;
        const float* gx = g_gatesx + ((size_t)t * BB + bb) * G4H;
        float gi = acc[0][lane] + gx[0 * HH + j];
        float gf = acc[1][lane] + gx[1 * HH + j];
        float gg = acc[2][lane] + gx[2 * HH + j];
        float go = acc[3][lane] + gx[3 * HH + j];
        float cold = g_c[bb * HH + j];
        float cn = sigf(gf) * cold + sigf(gi) * tanhf(gg);
        float hn = sigf(go) * tanhf(cn);
        g_c[bb * HH + j] = cn;
        g_act[par ^ 1][bb * RLEN + 256 + j] = hn;
        g_hall[((size_t)t * BB + bb) * HH + j] = hn;
    }
}

// -------------------- K2: wide interface GEMV (grid 118, block 256) -------------
__global__ void __launch_bounds__(256) k_itf2(const float* __restrict__ bint, int par) {
    __shared__ float hS[16 * 512];
    int tid = threadIdx.x;
    for (int i = tid; i < 2048; i += 256) {      // 2048 float4
        int b = i >> 7, q = i & 127;
        ((float4*)hS)[i] = ((const float4*)(g_act[par ^ 1] + b * RLEN + 256))[q];
    }
    __syncthreads();

    int lane = tid & 31, w = tid >> 5;
    int cbase = blockIdx.x * 4;
    #pragma unroll
    for (int i = 0; i < 8; i++) {
        int task = i * 8 + w;
        int c = cbase + (task >> 4);
        int b = task & 15;
        if (c < ITFD) {
            const float4* w4 = (const float4*)(g_WintT + (size_t)c * HH);
            const float4* h4 = (const float4*)(hS + b * 512);
            float acc = 0.f;
            #pragma unroll
            for (int q = 0; q < 4; q++) {
                float4 wv = w4[lane + q * 32];
                float4 hv = h4[lane + q * 32];
                acc += wv.x * hv.x + wv.y * hv.y + wv.z * hv.z + wv.w * hv.w;
            }
            #pragma unroll
            for (int o = 16; o; o >>= 1) acc += __shfl_xor_sync(0xffffffffu, acc, o);
            if (lane == 0) g_itf[b * ITFD + c] = acc + bint[c];
        }
    }
}

// -------------------- K3: per-batch write addressing (grid 16) ------------------
__global__ void __launch_bounds__(256) k_write(int par) {
    int b = blockIdx.x;
    int tid = threadIdx.x;
    __shared__ float itfs[ITFD + 1];
    __shared__ float uval[NN];
    __shared__ int   uidx[NN];
    __shared__ float allocv[NN];
    __shared__ float red[NN];
    __shared__ float karr[WWD];
    __shared__ float sc_knorm, sc_beta;

    for (int i = tid; i < ITFD; i += 256) itfs[i] = g_itf[b * ITFD + i];
    __syncthreads();

    float fg0 = sigf(itfs[O_FG + 0]);
    float fg1 = sigf(itfs[O_FG + 1]);
    float fg2 = sigf(itfs[O_FG + 2]);
    float fg3 = sigf(itfs[O_FG + 3]);
    float ag  = sigf(itfs[O_AG]);
    float wg  = sigf(itfs[O_WG]);

    int n = tid;
    float psi = 1.f;
    psi *= (1.f - fg0 * g_wr[(b * RR + 0) * NN + n]);
    psi *= (1.f - fg1 * g_wr[(b * RR + 1) * NN + n]);
    psi *= (1.f - fg2 * g_wr[(b * RR + 2) * NN + n]);
    psi *= (1.f - fg3 * g_wr[(b * RR + 3) * NN + n]);
    float u = g_usage[b * NN + n];
    float wagg = g_ww[b * NN + n];  // NW=1
    float un = (u + wagg - u * wagg) * psi;
    g_usage[b * NN + n] = un;

    if (tid < WWD) karr[tid] = itfs[O_WK + tid];
    __syncthreads();
    if (tid == 0) {
        float ss = 0.f;
        for (int w = 0; w < WWD; w++) ss += karr[w] * karr[w];
        sc_knorm = sqrtf(ss) + EPSF;
        sc_beta  = oneplusf(itfs[O_WS]);
    }
    __syncthreads();

    float dot = 0.f, ss = 0.f;
    const float* Mrow = g_M + ((size_t)(b * NN) + n) * WWD;
    #pragma unroll 8
    for (int w = 0; w < WWD; w++) {
        float m = Mrow[w];
        dot += m * karr[w];
        ss += m * m;
    }
    float sim = (dot / sc_knorm) / (sqrtf(ss) + EPSF);
    float sco = sc_beta * sim;
    float mx = blk_max256(sco, red, tid);
    float e = expf(sco - mx);
    float sm = blk_sum256(e, red, tid);
    float cwv = e / sm;

    // stable bitonic sort ascending on (usage, index); shfl for jmp<32
    float v = un; int ix = tid;
    for (int k2 = 2; k2 <= NN; k2 <<= 1) {
        for (int jmp = k2 >> 1; jmp; jmp >>= 1) {
            bool up = ((tid & k2) == 0);
            float v2; int i2;
            if (jmp >= 32) {
                uval[tid] = v; uidx[tid] = ix;
                __syncthreads();
                v2 = uval[tid ^ jmp]; i2 = uidx[tid ^ jmp];
                __syncthreads();
            } else {
                v2 = __shfl_xor_sync(0xffffffffu, v, jmp);
                i2 = __shfl_xor_sync(0xffffffffu, ix, jmp);
            }
            bool lower = ((tid & jmp) == 0);
            bool iless = (v < v2) || (v == v2 && ix < i2);
            bool keep = (iless == (lower == up));
            if (!keep) { v = v2; ix = i2; }
        }
    }

    // exclusive product scan over sorted usage -> allocation
    {
        int lane = tid & 31, wid = tid >> 5;
        float p = v;
        #pragma unroll
        for (int o = 1; o < 32; o <<= 1) {
            float q = __shfl_up_sync(0xffffffffu, p, o);
            if (lane >= o) p *= q;
        }
        if (lane == 31) red[wid] = p;
        __syncthreads();
        if (tid == 0) {
            float a = 1.f;
            #pragma unroll
            for (int w = 0; w < 8; w++) { float q = red[w]; red[8 + w] = a; a *= q; }
        }
        __syncthreads();
        float tmp = __shfl_up_sync(0xffffffffu, p, 1);
        float exclw = (lane == 0) ? 1.f : tmp;
        float excl = red[8 + wid] * exclw;
        allocv[ix] = (1.f - v) * excl;
        __syncthreads();
    }

    float wwn = wg * (ag * allocv[tid] + (1.f - ag) * cwv);
    g_ww[b * NN + tid] = wwn;
    float wsum = blk_sum256(wwn, red, tid);
    float pold = g_prec[par][b * NN + tid];
    g_prec[par ^ 1][b * NN + tid] = (1.f - wsum) * pold + wwn;
}

// -------------------- K4: wide link+M update (grid 256 = 16b x 16ch) ------------
__global__ void __launch_bounds__(256) k_mem2(int par) {
    int blk = blockIdx.x;
    int b = blk >> 4, ch = blk & 15;
    int tid = threadIdx.x;
    __shared__ float sww[NN];
    __shared__ float sprec[NN];
    __shared__ float wr4[4][NN];
    __shared__ float er[WWD];
    __shared__ float vv[WWD];
    __shared__ float tile[16][260];

    sww[tid]   = g_ww[b * NN + tid];
    sprec[tid] = g_prec[par][b * NN + tid];
    #pragma unroll
    for (int r = 0; r < RR; r++) wr4[r][tid] = g_wr[(b * RR + r) * NN + tid];
    if (tid < WWD) {
        er[tid] = sigf(g_itf[b * ITFD + O_ER + tid]);
        vv[tid] = sigf(g_itf[b * ITFD + O_WV + tid]);
    }
    __syncthreads();

    float wwj = sww[tid];
    float prj = sprec[tid];
    float bp0 = 0.f, bp1 = 0.f, bp2 = 0.f, bp3 = 0.f;
    float* lbase = g_link + (size_t)b * (NN * NN);
    #pragma unroll 4
    for (int ii = 0; ii < 16; ii++) {
        int i = ch * 16 + ii;
        float wwi = sww[i];
        float l = lbase[(size_t)i * NN + tid];
        float nv = (1.f - wwi - wwj) * l + wwi * prj;
        if (i == tid) nv = 0.f;
        lbase[(size_t)i * NN + tid] = nv;
        tile[ii][tid] = nv;
        bp0 += nv * wr4[0][i];
        bp1 += nv * wr4[1][i];
        bp2 += nv * wr4[2][i];
        bp3 += nv * wr4[3][i];
    }
    g_bwdP[((b * NCH + ch) * 4 + 0) * NN + tid] = bp0;
    g_bwdP[((b * NCH + ch) * 4 + 1) * NN + tid] = bp1;
    g_bwdP[((b * NCH + ch) * 4 + 2) * NN + tid] = bp2;
    g_bwdP[((b * NCH + ch) * 4 + 3) * NN + tid] = bp3;
    __syncthreads();

    {
        int warp = tid >> 5, lane = tid & 31;
        #pragma unroll
        for (int q = 0; q < 2; q++) {
            int ii = warp * 2 + q;
            int i = ch * 16 + ii;
            float a0 = 0.f, a1 = 0.f, a2 = 0.f, a3 = 0.f;
            #pragma unroll
            for (int p = 0; p < 8; p++) {
                int jx = lane + p * 32;
                float lv = tile[ii][jx];
                a0 += lv * wr4[0][jx]; a1 += lv * wr4[1][jx];
                a2 += lv * wr4[2][jx]; a3 += lv * wr4[3][jx];
            }
            #pragma unroll
            for (int o = 16; o; o >>= 1) {
                a0 += __shfl_down_sync(0xffffffffu, a0, o);
                a1 += __shfl_down_sync(0xffffffffu, a1, o);
                a2 += __shfl_down_sync(0xffffffffu, a2, o);
                a3 += __shfl_down_sync(0xffffffffu, a3, o);
            }
            if (lane == 0) {
                g_fwd[(b * 4 + 0) * NN + i] = a0;
                g_fwd[(b * 4 + 1) * NN + i] = a1;
                g_fwd[(b * 4 + 2) * NN + i] = a2;
                g_fwd[(b * 4 + 3) * NN + i] = a3;
            }
        }
    }

    {
        int n = ch * 16 + (tid >> 4);
        int w0 = (tid & 15) * 4;
        float wwn = sww[n];
        float* Mp = g_M + ((size_t)(b * NN) + n) * WWD + w0;
        #pragma unroll
        for (int q = 0; q < 4; q++)
            Mp[q] = Mp[q] * (1.f - wwn * er[w0 + q]) + wwn * vv[w0 + q];
    }
}

// -------------------- K5: per-batch read combine (grid 16) ----------------------
__global__ void __launch_bounds__(256) k_read2(int t, int par) {
    int b = blockIdx.x;
    int tid = threadIdx.x;
    __shared__ float kn[RR][WWD];
    __shared__ float wr_s[RR][NN];
    __shared__ float red[64];
    __shared__ float betas[RR], knorm[RR], mbv[RR], mfv[RR], mcv[RR];

    const float* itf = g_itf + (size_t)b * ITFD;

    {
        int r = tid >> 6, w = tid & 63;
        kn[r][w] = itf[O_RK + r * WWD + w];
    }
    __syncthreads();
    if (tid < RR) {
        float ss2 = 0.f;
        for (int w = 0; w < WWD; w++) ss2 += kn[tid][w] * kn[tid][w];
        knorm[tid] = sqrtf(ss2) + EPSF;
        betas[tid] = oneplusf(itf[O_RS + tid]);
        float m0 = itf[O_MO + tid * 3 + 0];
        float m1 = itf[O_MO + tid * 3 + 1];
        float m2 = itf[O_MO + tid * 3 + 2];
        float mxm = fmaxf(m0, fmaxf(m1, m2));
        float e0 = expf(m0 - mxm), e1 = expf(m1 - mxm), e2 = expf(m2 - mxm);
        float s = e0 + e1 + e2;
        mbv[tid] = e0 / s; mfv[tid] = e1 / s; mcv[tid] = e2 / s;
    }
    __syncthreads();

    const float* Mrow = g_M + ((size_t)(b * NN) + tid) * WWD;
    float d0 = 0.f, d1 = 0.f, d2 = 0.f, d3 = 0.f, ss2 = 0.f;
    #pragma unroll 8
    for (int w = 0; w < WWD; w++) {
        float m = Mrow[w];
        ss2 += m * m;
        d0 += m * kn[0][w]; d1 += m * kn[1][w]; d2 += m * kn[2][w]; d3 += m * kn[3][w];
    }
    float inv = 1.f / (sqrtf(ss2) + EPSF);
    float scv[4], m4[4];
    scv[0] = betas[0] * (d0 / knorm[0]) * inv;
    scv[1] = betas[1] * (d1 / knorm[1]) * inv;
    scv[2] = betas[2] * (d2 / knorm[2]) * inv;
    scv[3] = betas[3] * (d3 / knorm[3]) * inv;
    #pragma unroll
    for (int r = 0; r < 4; r++) m4[r] = scv[r];
    red4op(m4, true, red);
    float e4[4], s4[4];
    #pragma unroll
    for (int r = 0; r < 4; r++) { e4[r] = expf(scv[r] - m4[r]); s4[r] = e4[r]; }
    red4op(s4, false, red);

    float wrn[4];
    #pragma unroll
    for (int r = 0; r < 4; r++) {
        float bwd = 0.f;
        #pragma unroll
        for (int ch = 0; ch < NCH; ch++)
            bwd += g_bwdP[((b * NCH + ch) * 4 + r) * NN + tid];
        float fw = g_fwd[(b * 4 + r) * NN + tid];
        float cr = e4[r] / s4[r];
        wrn[r] = mbv[r] * bwd + mfv[r] * fw + mcv[r] * cr;
    }
    #pragma unroll
    for (int r = 0; r < 4; r++) {
        wr_s[r][tid] = wrn[r];
        g_wr[(b * RR + r) * NN + tid] = wrn[r];
    }
    __syncthreads();

    // read words -> combined activation buffer (rw cols [0,256)) + rwall
    {
        int r = tid >> 6, w = tid & 63;
        float acc = 0.f;
        for (int n2 = 0; n2 < NN; n2++)
            acc += wr_s[r][n2] * g_M[((size_t)(b * NN) + n2) * WWD + w];
        g_act[par ^ 1][b * RLEN + r * 64 + w] = acc;
        g_rwall[((size_t)t * BB + b) * (RR * WWD) + r * WWD + w] = acc;
    }
}

// -------------------- K6: batched output GEMM (verbatim) --------------------
__global__ void k_out(const float* __restrict__ Wout,
                      const float* __restrict__ bout,
                      float* __restrict__ out) {
    __shared__ float As[32][33];
    __shared__ float Bs[32][33];
    int tx = threadIdx.x & 15, ty = threadIdx.x >> 4;
    int tb0 = blockIdx.x * 32, o0 = blockIdx.y * 32;
    float acc00 = 0.f, acc01 = 0.f, acc10 = 0.f, acc11 = 0.f;
    for (int kt = 0; kt < 768; kt += 32) {
        for (int l = threadIdx.x; l < 1024; l += 256) {
            int mi = l >> 5, ki = l & 31;
            int k = kt + ki;
            int tb = tb0 + mi;
            float av = (k < 512) ? g_hall[(size_t)tb * HH + k]
                                 : g_rwall[(size_t)tb * (RR * WWD) + (k - 512)];
            As[mi][ki] = av;
            Bs[mi][ki] = Wout[(size_t)(o0 + mi) * 768 + k];
        }
        __syncthreads();
        #pragma unroll 8
        for (int ki = 0; ki < 32; ki++) {
            float a0 = As[ty * 2][ki], a1 = As[ty * 2 + 1][ki];
            float b0 = Bs[tx * 2][ki], b1 = Bs[tx * 2 + 1][ki];
            acc00 += a0 * b0; acc01 += a0 * b1;
            acc10 += a1 * b0; acc11 += a1 * b1;
        }
        __syncthreads();
    }
    int tb = tb0 + ty * 2, o = o0 + tx * 2;
    float bo0 = bout[o], bo1 = bout[o + 1];
    out[(size_t)tb * OUTD + o] = acc00 + bo0;
    out[(size_t)tb * OUTD + o + 1] = acc01 + bo1;
    out[(size_t)(tb + 1) * OUTD + o] = acc10 + bo0;
    out[(size_t)(tb + 1) * OUTD + o + 1] = acc11 + bo1;
}

// -------------------- host launch --------------------
extern "C" void kernel_launch(void* const* d_in, const int* in_sizes, int n_in,
                              void* d_out, int out_size) {
    const float* x    = (const float*)d_in[0];
    const float* Wih  = (const float*)d_in[1];
    const float* Whh  = (const float*)d_in[2];
    const float* bih  = (const float*)d_in[3];
    const float* bhh  = (const float*)d_in[4];
    const float* Wint = (const float*)d_in[5];
    const float* bint = (const float*)d_in[6];
    const float* Wout = (const float*)d_in[7];
    const float* bout = (const float*)d_in[8];
    float* out = (float*)d_out;

    void* p;
    cudaGetSymbolAddress(&p, g_act);   cudaMemsetAsync(p, 0, sizeof(float) * 2 * BB * RLEN);
    cudaGetSymbolAddress(&p, g_c);     cudaMemsetAsync(p, 0, sizeof(float) * BB * HH);
    cudaGetSymbolAddress(&p, g_M);     cudaMemsetAsync(p, 0, sizeof(float) * BB * NN * WWD);
    cudaGetSymbolAddress(&p, g_usage); cudaMemsetAsync(p, 0, sizeof(float) * BB * NN);
    cudaGetSymbolAddress(&p, g_link);  cudaMemsetAsync(p, 0, sizeof(float) * BB * NN * NN);
    cudaGetSymbolAddress(&p, g_prec);  cudaMemsetAsync(p, 0, sizeof(float) * 2 * BB * NN);
    cudaGetSymbolAddress(&p, g_wr);    cudaMemsetAsync(p, 0, sizeof(float) * BB * RR * NN);
    cudaGetSymbolAddress(&p, g_ww);    cudaMemsetAsync(p, 0, sizeof(float) * BB * NN);

    k_transpose<<<(ITFD * HH + 255) / 256, 256>>>(Wint);
    k_prep_wrec<<<(G4H * RLEN + 255) / 256, 256>>>(Wih, Whh);
    k_gatesx<<<dim3(32, 64), 256>>>(x, Wih, bih, bhh);

    for (int t = 0; t < TT; t++) {
        int par = t & 1;
        k_lstm<<<512, 256>>>(t, par);
        k_itf2<<<118, 256>>>(bint, par);
        k_write<<<16, 256>>>(par);
        k_mem2<<<256, 256>>>(par);
        k_read2<<<16, 256>>>(t, par);
    }
    k_out<<<dim3(32, 8), 256>>>(Wout, bout, out);
}

// round 15
// speedup vs baseline: 1.3038x; 1.0299x over previous
#include <cuda_runtime.h>
#include <cuda_bf16.h>
#include <math.h>

#define BB    16
#define TT    64
#define IND   256
#define HH    512
#define NN    256
#define WWD   64
#define RR    4
#define OUTD  256
#define ITFD  471
#define G4H   2048   // 4*H
#define RLEN  768    // combined activation row: 256 (rw) + 512 (h)
#define NCH   16     // link row-chunks per batch (16 rows each)

// interface vector offsets
#define O_RK 0
#define O_RS 256
#define O_WK 260
#define O_WS 324
#define O_ER 325
#define O_WV 389
#define O_FG 453
#define O_AG 457
#define O_WG 458
#define O_MO 459
#define EPSF 1e-6f

// -------------------- persistent state --------------------
__device__ __align__(16) float g_act[2][BB * RLEN];   // [rw(256) | h(512)] per batch
__device__ __align__(16) float g_c[BB * HH];
__device__ __align__(16) float g_M[BB * NN * WWD];
__device__ __align__(16) float g_usage[BB * NN];
__device__ __align__(16) float g_link[BB * NN * NN];
__device__ __align__(16) float g_prec[2][BB * NN];
__device__ __align__(16) float g_wr[BB * RR * NN];
__device__ __align__(16) float g_ww[BB * NN];
__device__ __align__(16) float g_itf[BB * ITFD];
__device__ __align__(16) float g_hall[TT * BB * HH];
__device__ __align__(16) float g_rwall[TT * BB * RR * WWD];
__device__ __align__(16) float g_WintT[ITFD * HH];
__device__ __align__(16) float g_bwdP[BB * NCH * RR * NN];
__device__ __align__(16) float g_fwd[BB * RR * NN];
__device__ __align__(16) __nv_bfloat16 g_WrecH[G4H * RLEN];  // bf16 [2048][768]
__device__ __align__(16) float g_gatesx[TT * BB * G4H];  // x-part of gates + biases

// -------------------- helpers --------------------
__device__ __forceinline__ float sigf(float x) { return 1.f / (1.f + expf(-x)); }
__device__ __forceinline__ float softplusf(float x) {
    return fmaxf(x, 0.f) + log1pf(expf(-fabsf(x)));
}
__device__ __forceinline__ float oneplusf(float x) { return 1.f + softplusf(x); }

__device__ __forceinline__ float blk_max256(float v, float* red, int tid) {
    red[tid] = v; __syncthreads();
    for (int s = 128; s > 0; s >>= 1) {
        if (tid < s) red[tid] = fmaxf(red[tid], red[tid + s]);
        __syncthreads();
    }
    float r = red[0]; __syncthreads();
    return r;
}
__device__ __forceinline__ float blk_sum256(float v, float* red, int tid) {
    red[tid] = v; __syncthreads();
    for (int s = 128; s > 0; s >>= 1) {
        if (tid < s) red[tid] = red[tid] + red[tid + s];
        __syncthreads();
    }
    float r = red[0]; __syncthreads();
    return r;
}

__device__ __forceinline__ void red4op(float v[4], bool domax, volatile float* red) {
    int tid = threadIdx.x;
    #pragma unroll
    for (int r = 0; r < 4; r++)
        #pragma unroll
        for (int o = 16; o; o >>= 1) {
            float u = __shfl_xor_sync(0xffffffffu, v[r], o);
            v[r] = domax ? fmaxf(v[r], u) : (v[r] + u);
        }
    if ((tid & 31) == 0) {
        int w = tid >> 5;
        red[w * 4 + 0] = v[0]; red[w * 4 + 1] = v[1];
        red[w * 4 + 2] = v[2]; red[w * 4 + 3] = v[3];
    }
    __syncthreads();
    if (tid == 0) {
        #pragma unroll
        for (int r = 0; r < 4; r++) {
            float a = red[r];
            for (int w = 1; w < 8; w++) {
                float u = red[w * 4 + r];
                a = domax ? fmaxf(a, u) : (a + u);
            }
            red[40 + r] = a;
        }
    }
    __syncthreads();
    v[0] = red[40]; v[1] = red[41]; v[2] = red[42]; v[3] = red[43];
    __syncthreads();
}

// -------------------- prep kernels (one-time) --------------------
__global__ void k_transpose(const float* __restrict__ Wint) {
    int idx = blockIdx.x * 256 + threadIdx.x;
    if (idx < ITFD * HH) {
        int c = idx / HH;
        int k = idx - c * HH;
        g_WintT[idx] = Wint[(size_t)k * ITFD + c];
    }
}

__global__ void k_prep_wrec(const float* __restrict__ Wih,
                            const float* __restrict__ Whh) {
    int idx = blockIdx.x * 256 + threadIdx.x;
    if (idx < G4H * RLEN) {
        int row = idx / RLEN;
        int c = idx - row * RLEN;
        float v = (c < 256) ? Wih[(size_t)row * 512 + 256 + c]
                            : Whh[(size_t)row * 512 + (c - 256)];
        g_WrecH[idx] = __float2bfloat16(v);
    }
}

__global__ void k_gatesx(const float* __restrict__ x,
                         const float* __restrict__ Wih,
                         const float* __restrict__ bih,
                         const float* __restrict__ bhh) {
    __shared__ float As[32][33];
    __shared__ float Bs[32][33];
    int tx = threadIdx.x & 15, ty = threadIdx.x >> 4;
    int m0 = blockIdx.x * 32, n0 = blockIdx.y * 32;
    float a00 = 0.f, a01 = 0.f, a10 = 0.f, a11 = 0.f;
    for (int kt = 0; kt < 256; kt += 32) {
        for (int l = threadIdx.x; l < 1024; l += 256) {
            int mi = l >> 5, ki = l & 31;
            As[mi][ki] = x[(size_t)(m0 + mi) * IND + kt + ki];
            Bs[mi][ki] = Wih[(size_t)(n0 + mi) * 512 + kt + ki];
        }
        __syncthreads();
        #pragma unroll 8
        for (int ki = 0; ki < 32; ki++) {
            float x0 = As[ty * 2][ki], x1 = As[ty * 2 + 1][ki];
            float w0 = Bs[tx * 2][ki], w1 = Bs[tx * 2 + 1][ki];
            a00 += x0 * w0; a01 += x0 * w1;
            a10 += x1 * w0; a11 += x1 * w1;
        }
        __syncthreads();
    }
    int m = m0 + ty * 2, n = n0 + tx * 2;
    float c0 = bih[n] + bhh[n], c1 = bih[n + 1] + bhh[n + 1];
    g_gatesx[(size_t)m * G4H + n] = a00 + c0;
    g_gatesx[(size_t)m * G4H + n + 1] = a01 + c1;
    g_gatesx[(size_t)(m + 1) * G4H + n] = a10 + c0;
    g_gatesx[(size_t)(m + 1) * G4H + n + 1] = a11 + c1;
}

// -------------------- K1: LSTM recurrent, warp = 2 batches x 4 gates, bf16 W ----
// grid 512 (one j per block), block 256 = 8 warps -> 16 batches.
// Act: float4 at col p*128+lane*4 (512B/warp). Weights: uint2 (4xbf16, 8B) at the
// same columns (256B/warp = 2 lines). Pure intra-warp butterfly; no smem.
__device__ __forceinline__ void bf4(const uint2 u, float4& f) {
    __nv_bfloat162 lo = *reinterpret_cast<const __nv_bfloat162*>(&u.x);
    __nv_bfloat162 hi = *reinterpret_cast<const __nv_bfloat162*>(&u.y);
    float2 a = __bfloat1622float2(lo);
    float2 b = __bfloat1622float2(hi);
    f.x = a.x; f.y = a.y; f.z = b.x; f.w = b.y;
}

__global__ void __launch_bounds__(256) k_lstm(int t, int par) {
    int tid = threadIdx.x;
    int lane = tid & 31;
    int w = tid >> 5;           // warp -> batches 2w, 2w+1
    int j = blockIdx.x;
    int b0 = w * 2;

    const float4* a0 = (const float4*)(g_act[par] + (size_t)b0 * RLEN);
    const float4* a1 = (const float4*)(g_act[par] + (size_t)(b0 + 1) * RLEN);
    const uint2* w0 = (const uint2*)(g_WrecH + (size_t)(0 * HH + j) * RLEN);
    const uint2* w1 = (const uint2*)(g_WrecH + (size_t)(1 * HH + j) * RLEN);
    const uint2* w2 = (const uint2*)(g_WrecH + (size_t)(2 * HH + j) * RLEN);
    const uint2* w3 = (const uint2*)(g_WrecH + (size_t)(3 * HH + j) * RLEN);

    float acc[4][2] = {{0.f, 0.f}, {0.f, 0.f}, {0.f, 0.f}, {0.f, 0.f}};
    #pragma unroll
    for (int p = 0; p < 6; p++) {
        int idx = p * 32 + lane;
        float4 av0 = a0[idx];
        float4 av1 = a1[idx];
        float4 wv;
        bf4(w0[idx], wv);
        acc[0][0] += wv.x * av0.x + wv.y * av0.y + wv.z * av0.z + wv.w * av0.w;
        acc[0][1] += wv.x * av1.x + wv.y * av1.y + wv.z * av1.z + wv.w * av1.w;
        bf4(w1[idx], wv);
        acc[1][0] += wv.x * av0.x + wv.y * av0.y + wv.z * av0.z + wv.w * av0.w;
        acc[1][1] += wv.x * av1.x + wv.y * av1.y + wv.z * av1.z + wv.w * av1.w;
        bf4(w2[idx], wv);
        acc[2][0] += wv.x * av0.x + wv.y * av0.y + wv.z * av0.z + wv.w * av0.w;
        acc[2][1] += wv.x * av1.x + wv.y * av1.y + wv.z * av1.z + wv.w * av1.w;
        bf4(w3[idx], wv);
        acc[3][0] += wv.x * av0.x + wv.y * av0.y + wv.z * av0.z + wv.w * av0.w;
        acc[3][1] += wv.x * av1.x + wv.y * av1.y + wv.z * av1.z + wv.w * av1.w;
    }
    #pragma unroll
    for (int o = 16; o; o >>= 1) {
        #pragma unroll
        for (int g = 0; g < 4; g++) {
            acc[g][0] += __shfl_xor_sync(0xffffffffu, acc[g][0], o);
            acc[g][1] += __shfl_xor_sync(0xffffffffu, acc[g][1], o);
        }
    }
    if (lane < 2) {
        int bb = b0 + lane;
        const float* gx = g_gatesx + ((size_t)t * BB + bb) * G4H;
        float gi = acc[0][lane] + gx[0 * HH + j];
        float gf = acc[1][lane] + gx[1 * HH + j];
        float gg = acc[2][lane] + gx[2 * HH + j];
        float go = acc[3][lane] + gx[3 * HH + j];
        float cold = g_c[bb * HH + j];
        float cn = sigf(gf) * cold + sigf(gi) * tanhf(gg);
        float hn = sigf(go) * tanhf(cn);
        g_c[bb * HH + j] = cn;
        g_act[par ^ 1][bb * RLEN + 256 + j] = hn;
        g_hall[((size_t)t * BB + bb) * HH + j] = hn;
    }
}

// -------------------- K2: wide interface GEMV (grid 118, block 256) -------------
__global__ void __launch_bounds__(256) k_itf2(const float* __restrict__ bint, int par) {
    __shared__ float hS[16 * 512];
    int tid = threadIdx.x;
    for (int i = tid; i < 2048; i += 256) {      // 2048 float4
        int b = i >> 7, q = i & 127;
        ((float4*)hS)[i] = ((const float4*)(g_act[par ^ 1] + b * RLEN + 256))[q];
    }
    __syncthreads();

    int lane = tid & 31, w = tid >> 5;
    int cbase = blockIdx.x * 4;
    #pragma unroll
    for (int i = 0; i < 8; i++) {
        int task = i * 8 + w;
        int c = cbase + (task >> 4);
        int b = task & 15;
        if (c < ITFD) {
            const float4* w4 = (const float4*)(g_WintT + (size_t)c * HH);
            const float4* h4 = (const float4*)(hS + b * 512);
            float acc = 0.f;
            #pragma unroll
            for (int q = 0; q < 4; q++) {
                float4 wv = w4[lane + q * 32];
                float4 hv = h4[lane + q * 32];
                acc += wv.x * hv.x + wv.y * hv.y + wv.z * hv.z + wv.w * hv.w;
            }
            #pragma unroll
            for (int o = 16; o; o >>= 1) acc += __shfl_xor_sync(0xffffffffu, acc, o);
            if (lane == 0) g_itf[b * ITFD + c] = acc + bint[c];
        }
    }
}

// -------------------- K3: per-batch write addressing (grid 16) ------------------
__global__ void __launch_bounds__(256) k_write(int par) {
    int b = blockIdx.x;
    int tid = threadIdx.x;
    __shared__ float itfs[ITFD + 1];
    __shared__ float uval[NN];
    __shared__ int   uidx[NN];
    __shared__ float allocv[NN];
    __shared__ float red[NN];
    __shared__ float karr[WWD];
    __shared__ float sc_knorm, sc_beta;

    for (int i = tid; i < ITFD; i += 256) itfs[i] = g_itf[b * ITFD + i];
    __syncthreads();

    float fg0 = sigf(itfs[O_FG + 0]);
    float fg1 = sigf(itfs[O_FG + 1]);
    float fg2 = sigf(itfs[O_FG + 2]);
    float fg3 = sigf(itfs[O_FG + 3]);
    float ag  = sigf(itfs[O_AG]);
    float wg  = sigf(itfs[O_WG]);

    int n = tid;
    float psi = 1.f;
    psi *= (1.f - fg0 * g_wr[(b * RR + 0) * NN + n]);
    psi *= (1.f - fg1 * g_wr[(b * RR + 1) * NN + n]);
    psi *= (1.f - fg2 * g_wr[(b * RR + 2) * NN + n]);
    psi *= (1.f - fg3 * g_wr[(b * RR + 3) * NN + n]);
    float u = g_usage[b * NN + n];
    float wagg = g_ww[b * NN + n];  // NW=1
    float un = (u + wagg - u * wagg) * psi;
    g_usage[b * NN + n] = un;

    if (tid < WWD) karr[tid] = itfs[O_WK + tid];
    __syncthreads();
    if (tid == 0) {
        float ss = 0.f;
        for (int w = 0; w < WWD; w++) ss += karr[w] * karr[w];
        sc_knorm = sqrtf(ss) + EPSF;
        sc_beta  = oneplusf(itfs[O_WS]);
    }
    __syncthreads();

    float dot = 0.f, ss = 0.f;
    const float* Mrow = g_M + ((size_t)(b * NN) + n) * WWD;
    #pragma unroll 8
    for (int w = 0; w < WWD; w++) {
        float m = Mrow[w];
        dot += m * karr[w];
        ss += m * m;
    }
    float sim = (dot / sc_knorm) / (sqrtf(ss) + EPSF);
    float sco = sc_beta * sim;
    float mx = blk_max256(sco, red, tid);
    float e = expf(sco - mx);
    float sm = blk_sum256(e, red, tid);
    float cwv = e / sm;

    // stable bitonic sort ascending on (usage, index); shfl for jmp<32
    float v = un; int ix = tid;
    for (int k2 = 2; k2 <= NN; k2 <<= 1) {
        for (int jmp = k2 >> 1; jmp; jmp >>= 1) {
            bool up = ((tid & k2) == 0);
            float v2; int i2;
            if (jmp >= 32) {
                uval[tid] = v; uidx[tid] = ix;
                __syncthreads();
                v2 = uval[tid ^ jmp]; i2 = uidx[tid ^ jmp];
                __syncthreads();
            } else {
                v2 = __shfl_xor_sync(0xffffffffu, v, jmp);
                i2 = __shfl_xor_sync(0xffffffffu, ix, jmp);
            }
            bool lower = ((tid & jmp) == 0);
            bool iless = (v < v2) || (v == v2 && ix < i2);
            bool keep = (iless == (lower == up));
            if (!keep) { v = v2; ix = i2; }
        }
    }

    // exclusive product scan over sorted usage -> allocation
    {
        int lane = tid & 31, wid = tid >> 5;
        float p = v;
        #pragma unroll
        for (int o = 1; o < 32; o <<= 1) {
            float q = __shfl_up_sync(0xffffffffu, p, o);
            if (lane >= o) p *= q;
        }
        if (lane == 31) red[wid] = p;
        __syncthreads();
        if (tid == 0) {
            float a = 1.f;
            #pragma unroll
            for (int w = 0; w < 8; w++) { float q = red[w]; red[8 + w] = a; a *= q; }
        }
        __syncthreads();
        float tmp = __shfl_up_sync(0xffffffffu, p, 1);
        float exclw = (lane == 0) ? 1.f : tmp;
        float excl = red[8 + wid] * exclw;
        allocv[ix] = (1.f - v) * excl;
        __syncthreads();
    }

    float wwn = wg * (ag * allocv[tid] + (1.f - ag) * cwv);
    g_ww[b * NN + tid] = wwn;
    float wsum = blk_sum256(wwn, red, tid);
    float pold = g_prec[par][b * NN + tid];
    g_prec[par ^ 1][b * NN + tid] = (1.f - wsum) * pold + wwn;
}

// -------------------- K4: wide link+M update (grid 256 = 16b x 16ch) ------------
__global__ void __launch_bounds__(256) k_mem2(int par) {
    int blk = blockIdx.x;
    int b = blk >> 4, ch = blk & 15;
    int tid = threadIdx.x;
    __shared__ float sww[NN];
    __shared__ float sprec[NN];
    __shared__ float wr4[4][NN];
    __shared__ float er[WWD];
    __shared__ float vv[WWD];
    __shared__ float tile[16][260];

    sww[tid]   = g_ww[b * NN + tid];
    sprec[tid] = g_prec[par][b * NN + tid];
    #pragma unroll
    for (int r = 0; r < RR; r++) wr4[r][tid] = g_wr[(b * RR + r) * NN + tid];
    if (tid < WWD) {
        er[tid] = sigf(g_itf[b * ITFD + O_ER + tid]);
        vv[tid] = sigf(g_itf[b * ITFD + O_WV + tid]);
    }
    __syncthreads();

    float wwj = sww[tid];
    float prj = sprec[tid];
    float bp0 = 0.f, bp1 = 0.f, bp2 = 0.f, bp3 = 0.f;
    float* lbase = g_link + (size_t)b * (NN * NN);
    #pragma unroll 4
    for (int ii = 0; ii < 16; ii++) {
        int i = ch * 16 + ii;
        float wwi = sww[i];
        float l = lbase[(size_t)i * NN + tid];
        float nv = (1.f - wwi - wwj) * l + wwi * prj;
        if (i == tid) nv = 0.f;
        lbase[(size_t)i * NN + tid] = nv;
        tile[ii][tid] = nv;
        bp0 += nv * wr4[0][i];
        bp1 += nv * wr4[1][i];
        bp2 += nv * wr4[2][i];
        bp3 += nv * wr4[3][i];
    }
    g_bwdP[((b * NCH + ch) * 4 + 0) * NN + tid] = bp0;
    g_bwdP[((b * NCH + ch) * 4 + 1) * NN + tid] = bp1;
    g_bwdP[((b * NCH + ch) * 4 + 2) * NN + tid] = bp2;
    g_bwdP[((b * NCH + ch) * 4 + 3) * NN + tid] = bp3;
    __syncthreads();

    {
        int warp = tid >> 5, lane = tid & 31;
        #pragma unroll
        for (int q = 0; q < 2; q++) {
            int ii = warp * 2 + q;
            int i = ch * 16 + ii;
            float a0 = 0.f, a1 = 0.f, a2 = 0.f, a3 = 0.f;
            #pragma unroll
            for (int p = 0; p < 8; p++) {
                int jx = lane + p * 32;
                float lv = tile[ii][jx];
                a0 += lv * wr4[0][jx]; a1 += lv * wr4[1][jx];
                a2 += lv * wr4[2][jx]; a3 += lv * wr4[3][jx];
            }
            #pragma unroll
            for (int o = 16; o; o >>= 1) {
                a0 += __shfl_down_sync(0xffffffffu, a0, o);
                a1 += __shfl_down_sync(0xffffffffu, a1, o);
                a2 += __shfl_down_sync(0xffffffffu, a2, o);
                a3 += __shfl_down_sync(0xffffffffu, a3, o);
            }
            if (lane == 0) {
                g_fwd[(b * 4 + 0) * NN + i] = a0;
                g_fwd[(b * 4 + 1) * NN + i] = a1;
                g_fwd[(b * 4 + 2) * NN + i] = a2;
                g_fwd[(b * 4 + 3) * NN + i] = a3;
            }
        }
    }

    {
        int n = ch * 16 + (tid >> 4);
        int w0 = (tid & 15) * 4;
        float wwn = sww[n];
        float* Mp = g_M + ((size_t)(b * NN) + n) * WWD + w0;
        #pragma unroll
        for (int q = 0; q < 4; q++)
            Mp[q] = Mp[q] * (1.f - wwn * er[w0 + q]) + wwn * vv[w0 + q];
    }
}

// -------------------- K5: per-batch read combine (grid 16) ----------------------
__global__ void __launch_bounds__(256) k_read2(int t, int par) {
    int b = blockIdx.x;
    int tid = threadIdx.x;
    __shared__ float kn[RR][WWD];
    __shared__ float wr_s[RR][NN];
    __shared__ float red[64];
    __shared__ float betas[RR], knorm[RR], mbv[RR], mfv[RR], mcv[RR];

    const float* itf = g_itf + (size_t)b * ITFD;

    {
        int r = tid >> 6, w = tid & 63;
        kn[r][w] = itf[O_RK + r * WWD + w];
    }
    __syncthreads();
    if (tid < RR) {
        float ss2 = 0.f;
        for (int w = 0; w < WWD; w++) ss2 += kn[tid][w] * kn[tid][w];
        knorm[tid] = sqrtf(ss2) + EPSF;
        betas[tid] = oneplusf(itf[O_RS + tid]);
        float m0 = itf[O_MO + tid * 3 + 0];
        float m1 = itf[O_MO + tid * 3 + 1];
        float m2 = itf[O_MO + tid * 3 + 2];
        float mxm = fmaxf(m0, fmaxf(m1, m2));
        float e0 = expf(m0 - mxm), e1 = expf(m1 - mxm), e2 = expf(m2 - mxm);
        float s = e0 + e1 + e2;
        mbv[tid] = e0 / s; mfv[tid] = e1 / s; mcv[tid] = e2 / s;
    }
    __syncthreads();

    const float* Mrow = g_M + ((size_t)(b * NN) + tid) * WWD;
    float d0 = 0.f, d1 = 0.f, d2 = 0.f, d3 = 0.f, ss2 = 0.f;
    #pragma unroll 8
    for (int w = 0; w < WWD; w++) {
        float m = Mrow[w];
        ss2 += m * m;
        d0 += m * kn[0][w]; d1 += m * kn[1][w]; d2 += m * kn[2][w]; d3 += m * kn[3][w];
    }
    float inv = 1.f / (sqrtf(ss2) + EPSF);
    float scv[4], m4[4];
    scv[0] = betas[0] * (d0 / knorm[0]) * inv;
    scv[1] = betas[1] * (d1 / knorm[1]) * inv;
    scv[2] = betas[2] * (d2 / knorm[2]) * inv;
    scv[3] = betas[3] * (d3 / knorm[3]) * inv;
    #pragma unroll
    for (int r = 0; r < 4; r++) m4[r] = scv[r];
    red4op(m4, true, red);
    float e4[4], s4[4];
    #pragma unroll
    for (int r = 0; r < 4; r++) { e4[r] = expf(scv[r] - m4[r]); s4[r] = e4[r]; }
    red4op(s4, false, red);

    float wrn[4];
    #pragma unroll
    for (int r = 0; r < 4; r++) {
        float bwd = 0.f;
        #pragma unroll
        for (int ch = 0; ch < NCH; ch++)
            bwd += g_bwdP[((b * NCH + ch) * 4 + r) * NN + tid];
        float fw = g_fwd[(b * 4 + r) * NN + tid];
        float cr = e4[r] / s4[r];
        wrn[r] = mbv[r] * bwd + mfv[r] * fw + mcv[r] * cr;
    }
    #pragma unroll
    for (int r = 0; r < 4; r++) {
        wr_s[r][tid] = wrn[r];
        g_wr[(b * RR + r) * NN + tid] = wrn[r];
    }
    __syncthreads();

    // read words -> combined activation buffer (rw cols [0,256)) + rwall
    {
        int r = tid >> 6, w = tid & 63;
        float acc = 0.f;
        for (int n2 = 0; n2 < NN; n2++)
            acc += wr_s[r][n2] * g_M[((size_t)(b * NN) + n2) * WWD + w];
        g_act[par ^ 1][b * RLEN + r * 64 + w] = acc;
        g_rwall[((size_t)t * BB + b) * (RR * WWD) + r * WWD + w] = acc;
    }
}

// -------------------- K6: batched output GEMM (verbatim) --------------------
__global__ void k_out(const float* __restrict__ Wout,
                      const float* __restrict__ bout,
                      float* __restrict__ out) {
    __shared__ float As[32][33];
    __shared__ float Bs[32][33];
    int tx = threadIdx.x & 15, ty = threadIdx.x >> 4;
    int tb0 = blockIdx.x * 32, o0 = blockIdx.y * 32;
    float acc00 = 0.f, acc01 = 0.f, acc10 = 0.f, acc11 = 0.f;
    for (int kt = 0; kt < 768; kt += 32) {
        for (int l = threadIdx.x; l < 1024; l += 256) {
            int mi = l >> 5, ki = l & 31;
            int k = kt + ki;
            int tb = tb0 + mi;
            float av = (k < 512) ? g_hall[(size_t)tb * HH + k]
                                 : g_rwall[(size_t)tb * (RR * WWD) + (k - 512)];
            As[mi][ki] = av;
            Bs[mi][ki] = Wout[(size_t)(o0 + mi) * 768 + k];
        }
        __syncthreads();
        #pragma unroll 8
        for (int ki = 0; ki < 32; ki++) {
            float a0 = As[ty * 2][ki], a1 = As[ty * 2 + 1][ki];
            float b0 = Bs[tx * 2][ki], b1 = Bs[tx * 2 + 1][ki];
            acc00 += a0 * b0; acc01 += a0 * b1;
            acc10 += a1 * b0; acc11 += a1 * b1;
        }
        __syncthreads();
    }
    int tb = tb0 + ty * 2, o = o0 + tx * 2;
    float bo0 = bout[o], bo1 = bout[o + 1];
    out[(size_t)tb * OUTD + o] = acc00 + bo0;
    out[(size_t)tb * OUTD + o + 1] = acc01 + bo1;
    out[(size_t)(tb + 1) * OUTD + o] = acc10 + bo0;
    out[(size_t)(tb + 1) * OUTD + o + 1] = acc11 + bo1;
}

// -------------------- host launch --------------------
extern "C" void kernel_launch(void* const* d_in, const int* in_sizes, int n_in,
                              void* d_out, int out_size) {
    const float* x    = (const float*)d_in[0];
    const float* Wih  = (const float*)d_in[1];
    const float* Whh  = (const float*)d_in[2];
    const float* bih  = (const float*)d_in[3];
    const float* bhh  = (const float*)d_in[4];
    const float* Wint = (const float*)d_in[5];
    const float* bint = (const float*)d_in[6];
    const float* Wout = (const float*)d_in[7];
    const float* bout = (const float*)d_in[8];
    float* out = (float*)d_out;

    void* p;
    cudaGetSymbolAddress(&p, g_act);   cudaMemsetAsync(p, 0, sizeof(float) * 2 * BB * RLEN);
    cudaGetSymbolAddress(&p, g_c);     cudaMemsetAsync(p, 0, sizeof(float) * BB * HH);
    cudaGetSymbolAddress(&p, g_M);     cudaMemsetAsync(p, 0, sizeof(float) * BB * NN * WWD);
    cudaGetSymbolAddress(&p, g_usage); cudaMemsetAsync(p, 0, sizeof(float) * BB * NN);
    cudaGetSymbolAddress(&p, g_link);  cudaMemsetAsync(p, 0, sizeof(float) * BB * NN * NN);
    cudaGetSymbolAddress(&p, g_prec);  cudaMemsetAsync(p, 0, sizeof(float) * 2 * BB * NN);
    cudaGetSymbolAddress(&p, g_wr);    cudaMemsetAsync(p, 0, sizeof(float) * BB * RR * NN);
    cudaGetSymbolAddress(&p, g_ww);    cudaMemsetAsync(p, 0, sizeof(float) * BB * NN);

    k_transpose<<<(ITFD * HH + 255) / 256, 256>>>(Wint);
    k_prep_wrec<<<(G4H * RLEN + 255) / 256, 256>>>(Wih, Whh);
    k_gatesx<<<dim3(32, 64), 256>>>(x, Wih, bih, bhh);

    for (int t = 0; t < TT; t++) {
        int par = t & 1;
        k_lstm<<<512, 256>>>(t, par);
        k_itf2<<<118, 256>>>(bint, par);
        k_write<<<16, 256>>>(par);
        k_mem2<<<256, 256>>>(par);
        k_read2<<<16, 256>>>(t, par);
    }
    k_out<<<dim3(32, 8), 256>>>(Wout, bout, out);
}

// round 16
// speedup vs baseline: 1.3058x; 1.0015x over previous
#include <cuda_runtime.h>
#include <cuda_bf16.h>
#include <math.h>

#define BB    16
#define TT    64
#define IND   256
#define HH    512
#define NN    256
#define WWD   64
#define RR    4
#define OUTD  256
#define ITFD  471
#define G4H   2048   // 4*H
#define RLEN  768    // combined activation row: 256 (rw) + 512 (h)
#define NCH   16     // link row-chunks per batch (16 rows each)

// interface vector offsets
#define O_RK 0
#define O_RS 256
#define O_WK 260
#define O_WS 324
#define O_ER 325
#define O_WV 389
#define O_FG 453
#define O_AG 457
#define O_WG 458
#define O_MO 459
#define EPSF 1e-6f

// -------------------- persistent state --------------------
__device__ __align__(16) float g_act[2][BB * RLEN];   // [rw(256) | h(512)] per batch
__device__ __align__(16) float g_c[BB * HH];
__device__ __align__(16) float g_M[2][BB * NN * WWD];   // ping-pong
__device__ __align__(16) float g_usage[2][BB * NN];     // ping-pong
__device__ __align__(16) float g_link[BB * NN * NN];
__device__ __align__(16) float g_prec[2][BB * NN];
__device__ __align__(16) float g_wr[BB * RR * NN];
__device__ __align__(16) float g_ww[2][BB * NN];        // ping-pong
__device__ __align__(16) float g_itf[BB * ITFD];
__device__ __align__(16) float g_hall[TT * BB * HH];
__device__ __align__(16) float g_rwall[TT * BB * RR * WWD];
__device__ __align__(16) float g_WintT[ITFD * HH];
__device__ __align__(16) float g_bwdP[BB * NCH * RR * NN];
__device__ __align__(16) float g_fwd[BB * RR * NN];
__device__ __align__(16) __nv_bfloat16 g_WrecH[G4H * RLEN];
__device__ __align__(16) float g_gatesx[TT * BB * G4H];

// -------------------- helpers --------------------
__device__ __forceinline__ float sigf(float x) { return 1.f / (1.f + expf(-x)); }
__device__ __forceinline__ float softplusf(float x) {
    return fmaxf(x, 0.f) + log1pf(expf(-fabsf(x)));
}
__device__ __forceinline__ float oneplusf(float x) { return 1.f + softplusf(x); }

__device__ __forceinline__ float blk_max256(float v, float* red, int tid) {
    red[tid] = v; __syncthreads();
    for (int s = 128; s > 0; s >>= 1) {
        if (tid < s) red[tid] = fmaxf(red[tid], red[tid + s]);
        __syncthreads();
    }
    float r = red[0]; __syncthreads();
    return r;
}
__device__ __forceinline__ float blk_sum256(float v, float* red, int tid) {
    red[tid] = v; __syncthreads();
    for (int s = 128; s > 0; s >>= 1) {
        if (tid < s) red[tid] = red[tid] + red[tid + s];
        __syncthreads();
    }
    float r = red[0]; __syncthreads();
    return r;
}

__device__ __forceinline__ void red4op(float v[4], bool domax, volatile float* red) {
    int tid = threadIdx.x;
    #pragma unroll
    for (int r = 0; r < 4; r++)
        #pragma unroll
        for (int o = 16; o; o >>= 1) {
            float u = __shfl_xor_sync(0xffffffffu, v[r], o);
            v[r] = domax ? fmaxf(v[r], u) : (v[r] + u);
        }
    if ((tid & 31) == 0) {
        int w = tid >> 5;
        red[w * 4 + 0] = v[0]; red[w * 4 + 1] = v[1];
        red[w * 4 + 2] = v[2]; red[w * 4 + 3] = v[3];
    }
    __syncthreads();
    if (tid == 0) {
        #pragma unroll
        for (int r = 0; r < 4; r++) {
            float a = red[r];
            for (int w = 1; w < 8; w++) {
                float u = red[w * 4 + r];
                a = domax ? fmaxf(a, u) : (a + u);
            }
            red[40 + r] = a;
        }
    }
    __syncthreads();
    v[0] = red[40]; v[1] = red[41]; v[2] = red[42]; v[3] = red[43];
    __syncthreads();
}

// -------------------- prep kernels (one-time) --------------------
__global__ void k_transpose(const float* __restrict__ Wint) {
    int idx = blockIdx.x * 256 + threadIdx.x;
    if (idx < ITFD * HH) {
        int c = idx / HH;
        int k = idx - c * HH;
        g_WintT[idx] = Wint[(size_t)k * ITFD + c];
    }
}

__global__ void k_prep_wrec(const float* __restrict__ Wih,
                            const float* __restrict__ Whh) {
    int idx = blockIdx.x * 256 + threadIdx.x;
    if (idx < G4H * RLEN) {
        int row = idx / RLEN;
        int c = idx - row * RLEN;
        float v = (c < 256) ? Wih[(size_t)row * 512 + 256 + c]
                            : Whh[(size_t)row * 512 + (c - 256)];
        g_WrecH[idx] = __float2bfloat16(v);
    }
}

__global__ void k_gatesx(const float* __restrict__ x,
                         const float* __restrict__ Wih,
                         const float* __restrict__ bih,
                         const float* __restrict__ bhh) {
    __shared__ float As[32][33];
    __shared__ float Bs[32][33];
    int tx = threadIdx.x & 15, ty = threadIdx.x >> 4;
    int m0 = blockIdx.x * 32, n0 = blockIdx.y * 32;
    float a00 = 0.f, a01 = 0.f, a10 = 0.f, a11 = 0.f;
    for (int kt = 0; kt < 256; kt += 32) {
        for (int l = threadIdx.x; l < 1024; l += 256) {
            int mi = l >> 5, ki = l & 31;
            As[mi][ki] = x[(size_t)(m0 + mi) * IND + kt + ki];
            Bs[mi][ki] = Wih[(size_t)(n0 + mi) * 512 + kt + ki];
        }
        __syncthreads();
        #pragma unroll 8
        for (int ki = 0; ki < 32; ki++) {
            float x0 = As[ty * 2][ki], x1 = As[ty * 2 + 1][ki];
            float w0 = Bs[tx * 2][ki], w1 = Bs[tx * 2 + 1][ki];
            a00 += x0 * w0; a01 += x0 * w1;
            a10 += x1 * w0; a11 += x1 * w1;
        }
        __syncthreads();
    }
    int m = m0 + ty * 2, n = n0 + tx * 2;
    float c0 = bih[n] + bhh[n], c1 = bih[n + 1] + bhh[n + 1];
    g_gatesx[(size_t)m * G4H + n] = a00 + c0;
    g_gatesx[(size_t)m * G4H + n + 1] = a01 + c1;
    g_gatesx[(size_t)(m + 1) * G4H + n] = a10 + c0;
    g_gatesx[(size_t)(m + 1) * G4H + n + 1] = a11 + c1;
}

// -------------------- K1: LSTM recurrent (R15 verbatim) -------------------------
__device__ __forceinline__ void bf4(const uint2 u, float4& f) {
    __nv_bfloat162 lo = *reinterpret_cast<const __nv_bfloat162*>(&u.x);
    __nv_bfloat162 hi = *reinterpret_cast<const __nv_bfloat162*>(&u.y);
    float2 a = __bfloat1622float2(lo);
    float2 b = __bfloat1622float2(hi);
    f.x = a.x; f.y = a.y; f.z = b.x; f.w = b.y;
}

__global__ void __launch_bounds__(256) k_lstm(int t, int par) {
    int tid = threadIdx.x;
    int lane = tid & 31;
    int w = tid >> 5;
    int j = blockIdx.x;
    int b0 = w * 2;

    const float4* a0 = (const float4*)(g_act[par] + (size_t)b0 * RLEN);
    const float4* a1 = (const float4*)(g_act[par] + (size_t)(b0 + 1) * RLEN);
    const uint2* w0 = (const uint2*)(g_WrecH + (size_t)(0 * HH + j) * RLEN);
    const uint2* w1 = (const uint2*)(g_WrecH + (size_t)(1 * HH + j) * RLEN);
    const uint2* w2 = (const uint2*)(g_WrecH + (size_t)(2 * HH + j) * RLEN);
    const uint2* w3 = (const uint2*)(g_WrecH + (size_t)(3 * HH + j) * RLEN);

    float acc[4][2] = {{0.f, 0.f}, {0.f, 0.f}, {0.f, 0.f}, {0.f, 0.f}};
    #pragma unroll
    for (int p = 0; p < 6; p++) {
        int idx = p * 32 + lane;
        float4 av0 = a0[idx];
        float4 av1 = a1[idx];
        float4 wv;
        bf4(w0[idx], wv);
        acc[0][0] += wv.x * av0.x + wv.y * av0.y + wv.z * av0.z + wv.w * av0.w;
        acc[0][1] += wv.x * av1.x + wv.y * av1.y + wv.z * av1.z + wv.w * av1.w;
        bf4(w1[idx], wv);
        acc[1][0] += wv.x * av0.x + wv.y * av0.y + wv.z * av0.z + wv.w * av0.w;
        acc[1][1] += wv.x * av1.x + wv.y * av1.y + wv.z * av1.z + wv.w * av1.w;
        bf4(w2[idx], wv);
        acc[2][0] += wv.x * av0.x + wv.y * av0.y + wv.z * av0.z + wv.w * av0.w;
        acc[2][1] += wv.x * av1.x + wv.y * av1.y + wv.z * av1.z + wv.w * av1.w;
        bf4(w3[idx], wv);
        acc[3][0] += wv.x * av0.x + wv.y * av0.y + wv.z * av0.z + wv.w * av0.w;
        acc[3][1] += wv.x * av1.x + wv.y * av1.y + wv.z * av1.z + wv.w * av1.w;
    }
    #pragma unroll
    for (int o = 16; o; o >>= 1) {
        #pragma unroll
        for (int g = 0; g < 4; g++) {
            acc[g][0] += __shfl_xor_sync(0xffffffffu, acc[g][0], o);
            acc[g][1] += __shfl_xor_sync(0xffffffffu, acc[g][1], o);
        }
    }
    if (lane < 2) {
        int bb = b0 + lane;
        const float* gx = g_gatesx + ((size_t)t * BB + bb) * G4H;
        float gi = acc[0][lane] + gx[0 * HH + j];
        float gf = acc[1][lane] + gx[1 * HH + j];
        float gg = acc[2][lane] + gx[2 * HH + j];
        float go = acc[3][lane] + gx[3 * HH + j];
        float cold = g_c[bb * HH + j];
        float cn = sigf(gf) * cold + sigf(gi) * tanhf(gg);
        float hn = sigf(go) * tanhf(cn);
        g_c[bb * HH + j] = cn;
        g_act[par ^ 1][bb * RLEN + 256 + j] = hn;
        g_hall[((size_t)t * BB + bb) * HH + j] = hn;
    }
}

// -------------------- K2: wide interface GEMV (R15 verbatim) --------------------
__global__ void __launch_bounds__(256) k_itf2(const float* __restrict__ bint, int par) {
    __shared__ float hS[16 * 512];
    int tid = threadIdx.x;
    for (int i = tid; i < 2048; i += 256) {
        int b = i >> 7, q = i & 127;
        ((float4*)hS)[i] = ((const float4*)(g_act[par ^ 1] + b * RLEN + 256))[q];
    }
    __syncthreads();

    int lane = tid & 31, w = tid >> 5;
    int cbase = blockIdx.x * 4;
    #pragma unroll
    for (int i = 0; i < 8; i++) {
        int task = i * 8 + w;
        int c = cbase + (task >> 4);
        int b = task & 15;
        if (c < ITFD) {
            const float4* w4 = (const float4*)(g_WintT + (size_t)c * HH);
            const float4* h4 = (const float4*)(hS + b * 512);
            float acc = 0.f;
            #pragma unroll
            for (int q = 0; q < 4; q++) {
                float4 wv = w4[lane + q * 32];
                float4 hv = h4[lane + q * 32];
                acc += wv.x * hv.x + wv.y * hv.y + wv.z * hv.z + wv.w * hv.w;
            }
            #pragma unroll
            for (int o = 16; o; o >>= 1) acc += __shfl_xor_sync(0xffffffffu, acc, o);
            if (lane == 0) g_itf[b * ITFD + c] = acc + bint[c];
        }
    }
}

// -------------------- K3: FUSED write-addressing + link/M update ----------------
// grid 256 = 16 batches x 16 chunks. Every block redundantly computes its batch's
// write addressing (identical results; duplicate stores benign), then does its
// link chunk + bwd/fwd + M chunk. usage/ww/M ping-pong eliminate RAW races.
__global__ void __launch_bounds__(256) k_memw(int par) {
    int blk = blockIdx.x;
    int b = blk >> 4, ch = blk & 15;
    int tid = threadIdx.x;
    __shared__ float wr4[4][NN];
    __shared__ float sww[NN];
    __shared__ float uval[NN];
    __shared__ int   uidx[NN];
    __shared__ float allocv[NN];
    __shared__ float red[NN];
    __shared__ float karr[WWD];
    __shared__ float sc_knorm, sc_beta;
    __shared__ float tile[16][260];

    const float* itf = g_itf + (size_t)b * ITFD;

    #pragma unroll
    for (int r = 0; r < RR; r++) wr4[r][tid] = g_wr[(b * RR + r) * NN + tid];
    if (tid < WWD) karr[tid] = itf[O_WK + tid];
    __syncthreads();
    if (tid == 0) {
        float ss = 0.f;
        for (int w = 0; w < WWD; w++) ss += karr[w] * karr[w];
        sc_knorm = sqrtf(ss) + EPSF;
        sc_beta  = oneplusf(itf[O_WS]);
    }
    __syncthreads();

    float fg0 = sigf(itf[O_FG + 0]);
    float fg1 = sigf(itf[O_FG + 1]);
    float fg2 = sigf(itf[O_FG + 2]);
    float fg3 = sigf(itf[O_FG + 3]);
    float ag  = sigf(itf[O_AG]);
    float wg  = sigf(itf[O_WG]);

    // usage update (ping-pong)
    float psi = 1.f;
    psi *= (1.f - fg0 * wr4[0][tid]);
    psi *= (1.f - fg1 * wr4[1][tid]);
    psi *= (1.f - fg2 * wr4[2][tid]);
    psi *= (1.f - fg3 * wr4[3][tid]);
    float u = g_usage[par][b * NN + tid];
    float wagg = g_ww[par][b * NN + tid];  // NW=1
    float un = (u + wagg - u * wagg) * psi;
    g_usage[par ^ 1][b * NN + tid] = un;

    // content write scores on OLD memory plane
    const float* MrowOld = g_M[par] + ((size_t)(b * NN) + tid) * WWD;
    float dot = 0.f, ss = 0.f;
    #pragma unroll 8
    for (int w = 0; w < WWD; w++) {
        float m = MrowOld[w];
        dot += m * karr[w];
        ss += m * m;
    }
    float sim = (dot / sc_knorm) / (sqrtf(ss) + EPSF);
    float sco = sc_beta * sim;
    float mx = blk_max256(sco, red, tid);
    float e = expf(sco - mx);
    float sm = blk_sum256(e, red, tid);
    float cwv = e / sm;

    // stable bitonic sort ascending on (usage, index); shfl for jmp<32
    float v = un; int ix = tid;
    for (int k2 = 2; k2 <= NN; k2 <<= 1) {
        for (int jmp = k2 >> 1; jmp; jmp >>= 1) {
            bool up = ((tid & k2) == 0);
            float v2; int i2;
            if (jmp >= 32) {
                uval[tid] = v; uidx[tid] = ix;
                __syncthreads();
                v2 = uval[tid ^ jmp]; i2 = uidx[tid ^ jmp];
                __syncthreads();
            } else {
                v2 = __shfl_xor_sync(0xffffffffu, v, jmp);
                i2 = __shfl_xor_sync(0xffffffffu, ix, jmp);
            }
            bool lower = ((tid & jmp) == 0);
            bool iless = (v < v2) || (v == v2 && ix < i2);
            bool keep = (iless == (lower == up));
            if (!keep) { v = v2; ix = i2; }
        }
    }

    // exclusive product scan over sorted usage -> allocation
    {
        int lane = tid & 31, wid = tid >> 5;
        float p = v;
        #pragma unroll
        for (int o = 1; o < 32; o <<= 1) {
            float q = __shfl_up_sync(0xffffffffu, p, o);
            if (lane >= o) p *= q;
        }
        if (lane == 31) red[wid] = p;
        __syncthreads();
        if (tid == 0) {
            float a = 1.f;
            #pragma unroll
            for (int w = 0; w < 8; w++) { float q = red[w]; red[8 + w] = a; a *= q; }
        }
        __syncthreads();
        float tmp = __shfl_up_sync(0xffffffffu, p, 1);
        float exclw = (lane == 0) ? 1.f : tmp;
        float excl = red[8 + wid] * exclw;
        allocv[ix] = (1.f - v) * excl;
        __syncthreads();
    }

    float wwn = wg * (ag * allocv[tid] + (1.f - ag) * cwv);
    g_ww[par ^ 1][b * NN + tid] = wwn;   // duplicate identical stores across chunks
    sww[tid] = wwn;
    float wsum = blk_sum256(wwn, red, tid);
    float prj = g_prec[par][b * NN + tid];
    g_prec[par ^ 1][b * NN + tid] = (1.f - wsum) * prj + wwn;
    __syncthreads();

    // link update for rows [ch*16, +16); thread owns column j=tid; fused bwd
    float wwj = sww[tid];
    float bp0 = 0.f, bp1 = 0.f, bp2 = 0.f, bp3 = 0.f;
    float* lbase = g_link + (size_t)b * (NN * NN);
    #pragma unroll 4
    for (int ii = 0; ii < 16; ii++) {
        int i = ch * 16 + ii;
        float wwi = sww[i];
        float l = lbase[(size_t)i * NN + tid];
        float nv = (1.f - wwi - wwj) * l + wwi * prj;
        if (i == tid) nv = 0.f;
        lbase[(size_t)i * NN + tid] = nv;
        tile[ii][tid] = nv;
        bp0 += nv * wr4[0][i];
        bp1 += nv * wr4[1][i];
        bp2 += nv * wr4[2][i];
        bp3 += nv * wr4[3][i];
    }
    g_bwdP[((b * NCH + ch) * 4 + 0) * NN + tid] = bp0;
    g_bwdP[((b * NCH + ch) * 4 + 1) * NN + tid] = bp1;
    g_bwdP[((b * NCH + ch) * 4 + 2) * NN + tid] = bp2;
    g_bwdP[((b * NCH + ch) * 4 + 3) * NN + tid] = bp3;
    __syncthreads();

    // fwd over own rows (warp per 2 rows)
    {
        int warp = tid >> 5, lane = tid & 31;
        #pragma unroll
        for (int q = 0; q < 2; q++) {
            int ii = warp * 2 + q;
            int i = ch * 16 + ii;
            float a0 = 0.f, a1 = 0.f, a2 = 0.f, a3 = 0.f;
            #pragma unroll
            for (int p = 0; p < 8; p++) {
                int jx = lane + p * 32;
                float lv = tile[ii][jx];
                a0 += lv * wr4[0][jx]; a1 += lv * wr4[1][jx];
                a2 += lv * wr4[2][jx]; a3 += lv * wr4[3][jx];
            }
            #pragma unroll
            for (int o = 16; o; o >>= 1) {
                a0 += __shfl_down_sync(0xffffffffu, a0, o);
                a1 += __shfl_down_sync(0xffffffffu, a1, o);
                a2 += __shfl_down_sync(0xffffffffu, a2, o);
                a3 += __shfl_down_sync(0xffffffffu, a3, o);
            }
            if (lane == 0) {
                g_fwd[(b * 4 + 0) * NN + i] = a0;
                g_fwd[(b * 4 + 1) * NN + i] = a1;
                g_fwd[(b * 4 + 2) * NN + i] = a2;
                g_fwd[(b * 4 + 3) * NN + i] = a3;
            }
        }
    }

    // memory erase/write: rows [ch*16, +16), OLD plane -> NEW plane
    {
        int n = ch * 16 + (tid >> 4);
        int w0 = (tid & 15) * 4;
        float wwn2 = sww[n];
        const float* Mo = g_M[par] + ((size_t)(b * NN) + n) * WWD + w0;
        float* Mn = g_M[par ^ 1] + ((size_t)(b * NN) + n) * WWD + w0;
        #pragma unroll
        for (int q = 0; q < 4; q++) {
            float er = sigf(itf[O_ER + w0 + q]);
            float vv = sigf(itf[O_WV + w0 + q]);
            Mn[q] = Mo[q] * (1.f - wwn2 * er) + wwn2 * vv;
        }
    }
}

// -------------------- K4: per-batch read combine (grid 16) ----------------------
__global__ void __launch_bounds__(256) k_read2(int t, int par) {
    int b = blockIdx.x;
    int tid = threadIdx.x;
    __shared__ float kn[RR][WWD];
    __shared__ float wr_s[RR][NN];
    __shared__ float red[64];
    __shared__ float betas[RR], knorm[RR], mbv[RR], mfv[RR], mcv[RR];

    const float* itf = g_itf + (size_t)b * ITFD;
    const float* Mnew = g_M[par ^ 1];

    {
        int r = tid >> 6, w = tid & 63;
        kn[r][w] = itf[O_RK + r * WWD + w];
    }
    __syncthreads();
    if (tid < RR) {
        float ss2 = 0.f;
        for (int w = 0; w < WWD; w++) ss2 += kn[tid][w] * kn[tid][w];
        knorm[tid] = sqrtf(ss2) + EPSF;
        betas[tid] = oneplusf(itf[O_RS + tid]);
        float m0 = itf[O_MO + tid * 3 + 0];
        float m1 = itf[O_MO + tid * 3 + 1];
        float m2 = itf[O_MO + tid * 3 + 2];
        float mxm = fmaxf(m0, fmaxf(m1, m2));
        float e0 = expf(m0 - mxm), e1 = expf(m1 - mxm), e2 = expf(m2 - mxm);
        float s = e0 + e1 + e2;
        mbv[tid] = e0 / s; mfv[tid] = e1 / s; mcv[tid] = e2 / s;
    }
    __syncthreads();

    const float* Mrow = Mnew + ((size_t)(b * NN) + tid) * WWD;
    float d0 = 0.f, d1 = 0.f, d2 = 0.f, d3 = 0.f, ss2 = 0.f;
    #pragma unroll 8
    for (int w = 0; w < WWD; w++) {
        float m = Mrow[w];
        ss2 += m * m;
        d0 += m * kn[0][w]; d1 += m * kn[1][w]; d2 += m * kn[2][w]; d3 += m * kn[3][w];
    }
    float inv = 1.f / (sqrtf(ss2) + EPSF);
    float scv[4], m4[4];
    scv[0] = betas[0] * (d0 / knorm[0]) * inv;
    scv[1] = betas[1] * (d1 / knorm[1]) * inv;
    scv[2] = betas[2] * (d2 / knorm[2]) * inv;
    scv[3] = betas[3] * (d3 / knorm[3]) * inv;
    #pragma unroll
    for (int r = 0; r < 4; r++) m4[r] = scv[r];
    red4op(m4, true, red);
    float e4[4], s4[4];
    #pragma unroll
    for (int r = 0; r < 4; r++) { e4[r] = expf(scv[r] - m4[r]); s4[r] = e4[r]; }
    red4op(s4, false, red);

    float wrn[4];
    #pragma unroll
    for (int r = 0; r < 4; r++) {
        float bwd = 0.f;
        #pragma unroll
        for (int ch = 0; ch < NCH; ch++)
            bwd += g_bwdP[((b * NCH + ch) * 4 + r) * NN + tid];
        float fw = g_fwd[(b * 4 + r) * NN + tid];
        float cr = e4[r] / s4[r];
        wrn[r] = mbv[r] * bwd + mfv[r] * fw + mcv[r] * cr;
    }
    #pragma unroll
    for (int r = 0; r < 4; r++) {
        wr_s[r][tid] = wrn[r];
        g_wr[(b * RR + r) * NN + tid] = wrn[r];
    }
    __syncthreads();

    // read words -> combined activation buffer + rwall
    {
        int r = tid >> 6, w = tid & 63;
        float acc = 0.f;
        for (int n2 = 0; n2 < NN; n2++)
            acc += wr_s[r][n2] * Mnew[((size_t)(b * NN) + n2) * WWD + w];
        g_act[par ^ 1][b * RLEN + r * 64 + w] = acc;
        g_rwall[((size_t)t * BB + b) * (RR * WWD) + r * WWD + w] = acc;
    }
}

// -------------------- K6: batched output GEMM (verbatim) --------------------
__global__ void k_out(const float* __restrict__ Wout,
                      const float* __restrict__ bout,
                      float* __restrict__ out) {
    __shared__ float As[32][33];
    __shared__ float Bs[32][33];
    int tx = threadIdx.x & 15, ty = threadIdx.x >> 4;
    int tb0 = blockIdx.x * 32, o0 = blockIdx.y * 32;
    float acc00 = 0.f, acc01 = 0.f, acc10 = 0.f, acc11 = 0.f;
    for (int kt = 0; kt < 768; kt += 32) {
        for (int l = threadIdx.x; l < 1024; l += 256) {
            int mi = l >> 5, ki = l & 31;
            int k = kt + ki;
            int tb = tb0 + mi;
            float av = (k < 512) ? g_hall[(size_t)tb * HH + k]
                                 : g_rwall[(size_t)tb * (RR * WWD) + (k - 512)];
            As[mi][ki] = av;
            Bs[mi][ki] = Wout[(size_t)(o0 + mi) * 768 + k];
        }
        __syncthreads();
        #pragma unroll 8
        for (int ki = 0; ki < 32; ki++) {
            float a0 = As[ty * 2][ki], a1 = As[ty * 2 + 1][ki];
            float b0 = Bs[tx * 2][ki], b1 = Bs[tx * 2 + 1][ki];
            acc00 += a0 * b0; acc01 += a0 * b1;
            acc10 += a1 * b0; acc11 += a1 * b1;
        }
        __syncthreads();
    }
    int tb = tb0 + ty * 2, o = o0 + tx * 2;
    float bo0 = bout[o], bo1 = bout[o + 1];
    out[(size_t)tb * OUTD + o] = acc00 + bo0;
    out[(size_t)tb * OUTD + o + 1] = acc01 + bo1;
    out[(size_t)(tb + 1) * OUTD + o] = acc10 + bo0;
    out[(size_t)(tb + 1) * OUTD + o + 1] = acc11 + bo1;
}

// -------------------- host launch --------------------
extern "C" void kernel_launch(void* const* d_in, const int* in_sizes, int n_in,
                              void* d_out, int out_size) {
    const float* x    = (const float*)d_in[0];
    const float* Wih  = (const float*)d_in[1];
    const float* Whh  = (const float*)d_in[2];
    const float* bih  = (const float*)d_in[3];
    const float* bhh  = (const float*)d_in[4];
    const float* Wint = (const float*)d_in[5];
    const float* bint = (const float*)d_in[6];
    const float* Wout = (const float*)d_in[7];
    const float* bout = (const float*)d_in[8];
    float* out = (float*)d_out;

    void* p;
    cudaGetSymbolAddress(&p, g_act);   cudaMemsetAsync(p, 0, sizeof(float) * 2 * BB * RLEN);
    cudaGetSymbolAddress(&p, g_c);     cudaMemsetAsync(p, 0, sizeof(float) * BB * HH);
    cudaGetSymbolAddress(&p, g_M);     cudaMemsetAsync(p, 0, sizeof(float) * 2 * BB * NN * WWD);
    cudaGetSymbolAddress(&p, g_usage); cudaMemsetAsync(p, 0, sizeof(float) * 2 * BB * NN);
    cudaGetSymbolAddress(&p, g_link);  cudaMemsetAsync(p, 0, sizeof(float) * BB * NN * NN);
    cudaGetSymbolAddress(&p, g_prec);  cudaMemsetAsync(p, 0, sizeof(float) * 2 * BB * NN);
    cudaGetSymbolAddress(&p, g_wr);    cudaMemsetAsync(p, 0, sizeof(float) * BB * RR * NN);
    cudaGetSymbolAddress(&p, g_ww);    cudaMemsetAsync(p, 0, sizeof(float) * 2 * BB * NN);

    k_transpose<<<(ITFD * HH + 255) / 256, 256>>>(Wint);
    k_prep_wrec<<<(G4H * RLEN + 255) / 256, 256>>>(Wih, Whh);
    k_gatesx<<<dim3(32, 64), 256>>>(x, Wih, bih, bhh);

    for (int t = 0; t < TT; t++) {
        int par = t & 1;
        k_lstm<<<512, 256>>>(t, par);
        k_itf2<<<118, 256>>>(bint, par);
        k_memw<<<256, 256>>>(par);
        k_read2<<<16, 256>>>(t, par);
    }
    k_out<<<dim3(32, 8), 256>>>(Wout, bout, out);
}

// round 17
// speedup vs baseline: 1.4399x; 1.1027x over previous
#include <cuda_runtime.h>
#include <cuda_bf16.h>
#include <math.h>

#define BB    16
#define TT    64
#define IND   256
#define HH    512
#define NN    256
#define WWD   64
#define RR    4
#define OUTD  256
#define ITFD  471
#define G4H   2048   // 4*H
#define RLEN  768    // combined activation row: 256 (rw) + 512 (h)
#define NCH   16     // link row-chunks per batch (16 rows each)

// interface vector offsets
#define O_RK 0
#define O_RS 256
#define O_WK 260
#define O_WS 324
#define O_ER 325
#define O_WV 389
#define O_FG 453
#define O_AG 457
#define O_WG 458
#define O_MO 459
#define EPSF 1e-6f

// -------------------- persistent state --------------------
__device__ __align__(16) float g_act[2][BB * RLEN];   // [rw(256) | h(512)] per batch
__device__ __align__(16) float g_c[BB * HH];
__device__ __align__(16) float g_M[2][BB * NN * WWD];   // ping-pong
__device__ __align__(16) float g_usage[2][BB * NN];     // ping-pong
__device__ __align__(16) float g_link[BB * NN * NN];
__device__ __align__(16) float g_prec[2][BB * NN];
__device__ __align__(16) float g_wr[BB * RR * NN];
__device__ __align__(16) float g_ww[2][BB * NN];        // ping-pong
__device__ __align__(16) float g_itf[BB * ITFD];
__device__ __align__(16) float g_hall[TT * BB * HH];
__device__ __align__(16) float g_rwall[TT * BB * RR * WWD];
__device__ __align__(16) float g_WintT[ITFD * HH];
__device__ __align__(16) float g_bwdP[BB * NCH * RR * NN];
__device__ __align__(16) float g_fwd[BB * RR * NN];
__device__ __align__(16) __nv_bfloat16 g_WrecH[G4H * RLEN];
__device__ __align__(16) float g_gatesx[TT * BB * G4H];

// -------------------- helpers --------------------
__device__ __forceinline__ float sigf(float x) { return 1.f / (1.f + expf(-x)); }
__device__ __forceinline__ float softplusf(float x) {
    return fmaxf(x, 0.f) + log1pf(expf(-fabsf(x)));
}
__device__ __forceinline__ float oneplusf(float x) { return 1.f + softplusf(x); }

__device__ __forceinline__ float blk_max256(float v, float* red, int tid) {
    red[tid] = v; __syncthreads();
    for (int s = 128; s > 0; s >>= 1) {
        if (tid < s) red[tid] = fmaxf(red[tid], red[tid + s]);
        __syncthreads();
    }
    float r = red[0]; __syncthreads();
    return r;
}
__device__ __forceinline__ float blk_sum256(float v, float* red, int tid) {
    red[tid] = v; __syncthreads();
    for (int s = 128; s > 0; s >>= 1) {
        if (tid < s) red[tid] = red[tid] + red[tid + s];
        __syncthreads();
    }
    float r = red[0]; __syncthreads();
    return r;
}

// -------------------- prep kernels (one-time) --------------------
__global__ void k_transpose(const float* __restrict__ Wint) {
    int idx = blockIdx.x * 256 + threadIdx.x;
    if (idx < ITFD * HH) {
        int c = idx / HH;
        int k = idx - c * HH;
        g_WintT[idx] = Wint[(size_t)k * ITFD + c];
    }
}

__global__ void k_prep_wrec(const float* __restrict__ Wih,
                            const float* __restrict__ Whh) {
    int idx = blockIdx.x * 256 + threadIdx.x;
    if (idx < G4H * RLEN) {
        int row = idx / RLEN;
        int c = idx - row * RLEN;
        float v = (c < 256) ? Wih[(size_t)row * 512 + 256 + c]
                            : Whh[(size_t)row * 512 + (c - 256)];
        g_WrecH[idx] = __float2bfloat16(v);
    }
}

__global__ void k_gatesx(const float* __restrict__ x,
                         const float* __restrict__ Wih,
                         const float* __restrict__ bih,
                         const float* __restrict__ bhh) {
    __shared__ float As[32][33];
    __shared__ float Bs[32][33];
    int tx = threadIdx.x & 15, ty = threadIdx.x >> 4;
    int m0 = blockIdx.x * 32, n0 = blockIdx.y * 32;
    float a00 = 0.f, a01 = 0.f, a10 = 0.f, a11 = 0.f;
    for (int kt = 0; kt < 256; kt += 32) {
        for (int l = threadIdx.x; l < 1024; l += 256) {
            int mi = l >> 5, ki = l & 31;
            As[mi][ki] = x[(size_t)(m0 + mi) * IND + kt + ki];
            Bs[mi][ki] = Wih[(size_t)(n0 + mi) * 512 + kt + ki];
        }
        __syncthreads();
        #pragma unroll 8
        for (int ki = 0; ki < 32; ki++) {
            float x0 = As[ty * 2][ki], x1 = As[ty * 2 + 1][ki];
            float w0 = Bs[tx * 2][ki], w1 = Bs[tx * 2 + 1][ki];
            a00 += x0 * w0; a01 += x0 * w1;
            a10 += x1 * w0; a11 += x1 * w1;
        }
        __syncthreads();
    }
    int m = m0 + ty * 2, n = n0 + tx * 2;
    float c0 = bih[n] + bhh[n], c1 = bih[n + 1] + bhh[n + 1];
    g_gatesx[(size_t)m * G4H + n] = a00 + c0;
    g_gatesx[(size_t)m * G4H + n + 1] = a01 + c1;
    g_gatesx[(size_t)(m + 1) * G4H + n] = a10 + c0;
    g_gatesx[(size_t)(m + 1) * G4H + n + 1] = a11 + c1;
}

// -------------------- K1: LSTM recurrent (R15 verbatim) -------------------------
__device__ __forceinline__ void bf4(const uint2 u, float4& f) {
    __nv_bfloat162 lo = *reinterpret_cast<const __nv_bfloat162*>(&u.x);
    __nv_bfloat162 hi = *reinterpret_cast<const __nv_bfloat162*>(&u.y);
    float2 a = __bfloat1622float2(lo);
    float2 b = __bfloat1622float2(hi);
    f.x = a.x; f.y = a.y; f.z = b.x; f.w = b.y;
}

__global__ void __launch_bounds__(256) k_lstm(int t, int par) {
    int tid = threadIdx.x;
    int lane = tid & 31;
    int w = tid >> 5;
    int j = blockIdx.x;
    int b0 = w * 2;

    const float4* a0 = (const float4*)(g_act[par] + (size_t)b0 * RLEN);
    const float4* a1 = (const float4*)(g_act[par] + (size_t)(b0 + 1) * RLEN);
    const uint2* w0 = (const uint2*)(g_WrecH + (size_t)(0 * HH + j) * RLEN);
    const uint2* w1 = (const uint2*)(g_WrecH + (size_t)(1 * HH + j) * RLEN);
    const uint2* w2 = (const uint2*)(g_WrecH + (size_t)(2 * HH + j) * RLEN);
    const uint2* w3 = (const uint2*)(g_WrecH + (size_t)(3 * HH + j) * RLEN);

    float acc[4][2] = {{0.f, 0.f}, {0.f, 0.f}, {0.f, 0.f}, {0.f, 0.f}};
    #pragma unroll
    for (int p = 0; p < 6; p++) {
        int idx = p * 32 + lane;
        float4 av0 = a0[idx];
        float4 av1 = a1[idx];
        float4 wv;
        bf4(w0[idx], wv);
        acc[0][0] += wv.x * av0.x + wv.y * av0.y + wv.z * av0.z + wv.w * av0.w;
        acc[0][1] += wv.x * av1.x + wv.y * av1.y + wv.z * av1.z + wv.w * av1.w;
        bf4(w1[idx], wv);
        acc[1][0] += wv.x * av0.x + wv.y * av0.y + wv.z * av0.z + wv.w * av0.w;
        acc[1][1] += wv.x * av1.x + wv.y * av1.y + wv.z * av1.z + wv.w * av1.w;
        bf4(w2[idx], wv);
        acc[2][0] += wv.x * av0.x + wv.y * av0.y + wv.z * av0.z + wv.w * av0.w;
        acc[2][1] += wv.x * av1.x + wv.y * av1.y + wv.z * av1.z + wv.w * av1.w;
        bf4(w3[idx], wv);
        acc[3][0] += wv.x * av0.x + wv.y * av0.y + wv.z * av0.z + wv.w * av0.w;
        acc[3][1] += wv.x * av1.x + wv.y * av1.y + wv.z * av1.z + wv.w * av1.w;
    }
    #pragma unroll
    for (int o = 16; o; o >>= 1) {
        #pragma unroll
        for (int g = 0; g < 4; g++) {
            acc[g][0] += __shfl_xor_sync(0xffffffffu, acc[g][0], o);
            acc[g][1] += __shfl_xor_sync(0xffffffffu, acc[g][1], o);
        }
    }
    if (lane < 2) {
        int bb = b0 + lane;
        const float* gx = g_gatesx + ((size_t)t * BB + bb) * G4H;
        float gi = acc[0][lane] + gx[0 * HH + j];
        float gf = acc[1][lane] + gx[1 * HH + j];
        float gg = acc[2][lane] + gx[2 * HH + j];
        float go = acc[3][lane] + gx[3 * HH + j];
        float cold = g_c[bb * HH + j];
        float cn = sigf(gf) * cold + sigf(gi) * tanhf(gg);
        float hn = sigf(go) * tanhf(cn);
        g_c[bb * HH + j] = cn;
        g_act[par ^ 1][bb * RLEN + 256 + j] = hn;
        g_hall[((size_t)t * BB + bb) * HH + j] = hn;
    }
}

// -------------------- K2: wide interface GEMV (R15 verbatim) --------------------
__global__ void __launch_bounds__(256) k_itf2(const float* __restrict__ bint, int par) {
    __shared__ float hS[16 * 512];
    int tid = threadIdx.x;
    for (int i = tid; i < 2048; i += 256) {
        int b = i >> 7, q = i & 127;
        ((float4*)hS)[i] = ((const float4*)(g_act[par ^ 1] + b * RLEN + 256))[q];
    }
    __syncthreads();

    int lane = tid & 31, w = tid >> 5;
    int cbase = blockIdx.x * 4;
    #pragma unroll
    for (int i = 0; i < 8; i++) {
        int task = i * 8 + w;
        int c = cbase + (task >> 4);
        int b = task & 15;
        if (c < ITFD) {
            const float4* w4 = (const float4*)(g_WintT + (size_t)c * HH);
            const float4* h4 = (const float4*)(hS + b * 512);
            float acc = 0.f;
            #pragma unroll
            for (int q = 0; q < 4; q++) {
                float4 wv = w4[lane + q * 32];
                float4 hv = h4[lane + q * 32];
                acc += wv.x * hv.x + wv.y * hv.y + wv.z * hv.z + wv.w * hv.w;
            }
            #pragma unroll
            for (int o = 16; o; o >>= 1) acc += __shfl_xor_sync(0xffffffffu, acc, o);
            if (lane == 0) g_itf[b * ITFD + c] = acc + bint[c];
        }
    }
}

// -------------------- K3: FUSED write-addressing + link/M update (R16 verbatim) -
__global__ void __launch_bounds__(256) k_memw(int par) {
    int blk = blockIdx.x;
    int b = blk >> 4, ch = blk & 15;
    int tid = threadIdx.x;
    __shared__ float wr4[4][NN];
    __shared__ float sww[NN];
    __shared__ float uval[NN];
    __shared__ int   uidx[NN];
    __shared__ float allocv[NN];
    __shared__ float red[NN];
    __shared__ float karr[WWD];
    __shared__ float sc_knorm, sc_beta;
    __shared__ float tile[16][260];

    const float* itf = g_itf + (size_t)b * ITFD;

    #pragma unroll
    for (int r = 0; r < RR; r++) wr4[r][tid] = g_wr[(b * RR + r) * NN + tid];
    if (tid < WWD) karr[tid] = itf[O_WK + tid];
    __syncthreads();
    if (tid == 0) {
        float ss = 0.f;
        for (int w = 0; w < WWD; w++) ss += karr[w] * karr[w];
        sc_knorm = sqrtf(ss) + EPSF;
        sc_beta  = oneplusf(itf[O_WS]);
    }
    __syncthreads();

    float fg0 = sigf(itf[O_FG + 0]);
    float fg1 = sigf(itf[O_FG + 1]);
    float fg2 = sigf(itf[O_FG + 2]);
    float fg3 = sigf(itf[O_FG + 3]);
    float ag  = sigf(itf[O_AG]);
    float wg  = sigf(itf[O_WG]);

    // usage update (ping-pong)
    float psi = 1.f;
    psi *= (1.f - fg0 * wr4[0][tid]);
    psi *= (1.f - fg1 * wr4[1][tid]);
    psi *= (1.f - fg2 * wr4[2][tid]);
    psi *= (1.f - fg3 * wr4[3][tid]);
    float u = g_usage[par][b * NN + tid];
    float wagg = g_ww[par][b * NN + tid];  // NW=1
    float un = (u + wagg - u * wagg) * psi;
    g_usage[par ^ 1][b * NN + tid] = un;

    // content write scores on OLD memory plane
    const float* MrowOld = g_M[par] + ((size_t)(b * NN) + tid) * WWD;
    float dot = 0.f, ss = 0.f;
    #pragma unroll 8
    for (int w = 0; w < WWD; w++) {
        float m = MrowOld[w];
        dot += m * karr[w];
        ss += m * m;
    }
    float sim = (dot / sc_knorm) / (sqrtf(ss) + EPSF);
    float sco = sc_beta * sim;
    float mx = blk_max256(sco, red, tid);
    float e = expf(sco - mx);
    float sm = blk_sum256(e, red, tid);
    float cwv = e / sm;

    // stable bitonic sort ascending on (usage, index); shfl for jmp<32
    float v = un; int ix = tid;
    for (int k2 = 2; k2 <= NN; k2 <<= 1) {
        for (int jmp = k2 >> 1; jmp; jmp >>= 1) {
            bool up = ((tid & k2) == 0);
            float v2; int i2;
            if (jmp >= 32) {
                uval[tid] = v; uidx[tid] = ix;
                __syncthreads();
                v2 = uval[tid ^ jmp]; i2 = uidx[tid ^ jmp];
                __syncthreads();
            } else {
                v2 = __shfl_xor_sync(0xffffffffu, v, jmp);
                i2 = __shfl_xor_sync(0xffffffffu, ix, jmp);
            }
            bool lower = ((tid & jmp) == 0);
            bool iless = (v < v2) || (v == v2 && ix < i2);
            bool keep = (iless == (lower == up));
            if (!keep) { v = v2; ix = i2; }
        }
    }

    // exclusive product scan over sorted usage -> allocation
    {
        int lane = tid & 31, wid = tid >> 5;
        float p = v;
        #pragma unroll
        for (int o = 1; o < 32; o <<= 1) {
            float q = __shfl_up_sync(0xffffffffu, p, o);
            if (lane >= o) p *= q;
        }
        if (lane == 31) red[wid] = p;
        __syncthreads();
        if (tid == 0) {
            float a = 1.f;
            #pragma unroll
            for (int w = 0; w < 8; w++) { float q = red[w]; red[8 + w] = a; a *= q; }
        }
        __syncthreads();
        float tmp = __shfl_up_sync(0xffffffffu, p, 1);
        float exclw = (lane == 0) ? 1.f : tmp;
        float excl = red[8 + wid] * exclw;
        allocv[ix] = (1.f - v) * excl;
        __syncthreads();
    }

    float wwn = wg * (ag * allocv[tid] + (1.f - ag) * cwv);
    g_ww[par ^ 1][b * NN + tid] = wwn;
    sww[tid] = wwn;
    float wsum = blk_sum256(wwn, red, tid);
    float prj = g_prec[par][b * NN + tid];
    g_prec[par ^ 1][b * NN + tid] = (1.f - wsum) * prj + wwn;
    __syncthreads();

    // link update for rows [ch*16, +16); thread owns column j=tid; fused bwd
    float wwj = sww[tid];
    float bp0 = 0.f, bp1 = 0.f, bp2 = 0.f, bp3 = 0.f;
    float* lbase = g_link + (size_t)b * (NN * NN);
    #pragma unroll 4
    for (int ii = 0; ii < 16; ii++) {
        int i = ch * 16 + ii;
        float wwi = sww[i];
        float l = lbase[(size_t)i * NN + tid];
        float nv = (1.f - wwi - wwj) * l + wwi * prj;
        if (i == tid) nv = 0.f;
        lbase[(size_t)i * NN + tid] = nv;
        tile[ii][tid] = nv;
        bp0 += nv * wr4[0][i];
        bp1 += nv * wr4[1][i];
        bp2 += nv * wr4[2][i];
        bp3 += nv * wr4[3][i];
    }
    g_bwdP[((b * NCH + ch) * 4 + 0) * NN + tid] = bp0;
    g_bwdP[((b * NCH + ch) * 4 + 1) * NN + tid] = bp1;
    g_bwdP[((b * NCH + ch) * 4 + 2) * NN + tid] = bp2;
    g_bwdP[((b * NCH + ch) * 4 + 3) * NN + tid] = bp3;
    __syncthreads();

    // fwd over own rows (warp per 2 rows)
    {
        int warp = tid >> 5, lane = tid & 31;
        #pragma unroll
        for (int q = 0; q < 2; q++) {
            int ii = warp * 2 + q;
            int i = ch * 16 + ii;
            float a0 = 0.f, a1 = 0.f, a2 = 0.f, a3 = 0.f;
            #pragma unroll
            for (int p = 0; p < 8; p++) {
                int jx = lane + p * 32;
                float lv = tile[ii][jx];
                a0 += lv * wr4[0][jx]; a1 += lv * wr4[1][jx];
                a2 += lv * wr4[2][jx]; a3 += lv * wr4[3][jx];
            }
            #pragma unroll
            for (int o = 16; o; o >>= 1) {
                a0 += __shfl_down_sync(0xffffffffu, a0, o);
                a1 += __shfl_down_sync(0xffffffffu, a1, o);
                a2 += __shfl_down_sync(0xffffffffu, a2, o);
                a3 += __shfl_down_sync(0xffffffffu, a3, o);
            }
            if (lane == 0) {
                g_fwd[(b * 4 + 0) * NN + i] = a0;
                g_fwd[(b * 4 + 1) * NN + i] = a1;
                g_fwd[(b * 4 + 2) * NN + i] = a2;
                g_fwd[(b * 4 + 3) * NN + i] = a3;
            }
        }
    }

    // memory erase/write: rows [ch*16, +16), OLD plane -> NEW plane
    {
        int n = ch * 16 + (tid >> 4);
        int w0 = (tid & 15) * 4;
        float wwn2 = sww[n];
        const float* Mo = g_M[par] + ((size_t)(b * NN) + n) * WWD + w0;
        float* Mn = g_M[par ^ 1] + ((size_t)(b * NN) + n) * WWD + w0;
        #pragma unroll
        for (int q = 0; q < 4; q++) {
            float er = sigf(itf[O_ER + w0 + q]);
            float vv = sigf(itf[O_WV + w0 + q]);
            Mn[q] = Mo[q] * (1.f - wwn2 * er) + wwn2 * vv;
        }
    }
}

// -------------------- K4: per-(batch,head) read combine (grid (16,4)) -----------
__global__ void __launch_bounds__(256) k_read3(int t, int par) {
    int b = blockIdx.x;
    int r = blockIdx.y;
    int tid = threadIdx.x;
    __shared__ float kn[WWD];
    __shared__ float wrsh[NN];
    __shared__ float red[NN];
    __shared__ float partial[4][WWD];
    __shared__ float sc[5];   // knorm, beta, mb, mf, mc

    const float* itf = g_itf + (size_t)b * ITFD;
    const float* Mnew = g_M[par ^ 1];

    if (tid < WWD) kn[tid] = itf[O_RK + r * WWD + tid];
    __syncthreads();
    if (tid == 0) {
        float ss = 0.f;
        for (int w = 0; w < WWD; w++) ss += kn[w] * kn[w];
        sc[0] = sqrtf(ss) + EPSF;
        sc[1] = oneplusf(itf[O_RS + r]);
        float m0 = itf[O_MO + r * 3 + 0];
        float m1 = itf[O_MO + r * 3 + 1];
        float m2 = itf[O_MO + r * 3 + 2];
        float mxm = fmaxf(m0, fmaxf(m1, m2));
        float e0 = expf(m0 - mxm), e1 = expf(m1 - mxm), e2 = expf(m2 - mxm);
        float s = e0 + e1 + e2;
        sc[2] = e0 / s; sc[3] = e1 / s; sc[4] = e2 / s;
    }
    __syncthreads();

    // content read score on NEW memory (own row n=tid)
    const float4* M4 = (const float4*)(Mnew + ((size_t)(b * NN) + tid) * WWD);
    float dot = 0.f, ssm = 0.f;
    #pragma unroll
    for (int q = 0; q < 16; q++) {
        float4 m = M4[q];
        int w = q * 4;
        ssm += m.x * m.x + m.y * m.y + m.z * m.z + m.w * m.w;
        dot += m.x * kn[w] + m.y * kn[w + 1] + m.z * kn[w + 2] + m.w * kn[w + 3];
    }
    float sco = sc[1] * (dot / sc[0]) / (sqrtf(ssm) + EPSF);
    float mx = blk_max256(sco, red, tid);
    float e = expf(sco - mx);
    float sm = blk_sum256(e, red, tid);
    float cr = e / sm;

    // bwd: sum chunk partials; fwd: direct load
    float bwd = 0.f;
    #pragma unroll
    for (int ch = 0; ch < NCH; ch++)
        bwd += g_bwdP[((b * NCH + ch) * 4 + r) * NN + tid];
    float fw = g_fwd[(b * 4 + r) * NN + tid];

    float wrn = sc[2] * bwd + sc[3] * fw + sc[4] * cr;
    g_wr[(b * RR + r) * NN + tid] = wrn;
    wrsh[tid] = wrn;
    __syncthreads();

    // read words: seg = tid>>6 covers n in [seg*64, +64); w = tid&63
    {
        int seg = tid >> 6, w = tid & 63;
        const float* Mb = Mnew + (size_t)b * (NN * WWD);
        float acc = 0.f;
        #pragma unroll 4
        for (int q = 0; q < 64; q++) {
            int n2 = seg * 64 + q;
            acc += wrsh[n2] * Mb[(size_t)n2 * WWD + w];
        }
        partial[seg][w] = acc;
    }
    __syncthreads();
    if (tid < WWD) {
        float acc = partial[0][tid] + partial[1][tid] + partial[2][tid] + partial[3][tid];
        g_act[par ^ 1][b * RLEN + r * 64 + tid] = acc;
        g_rwall[((size_t)t * BB + b) * (RR * WWD) + r * WWD + tid] = acc;
    }
}

// -------------------- K6: batched output GEMM (verbatim) --------------------
__global__ void k_out(const float* __restrict__ Wout,
                      const float* __restrict__ bout,
                      float* __restrict__ out) {
    __shared__ float As[32][33];
    __shared__ float Bs[32][33];
    int tx = threadIdx.x & 15, ty = threadIdx.x >> 4;
    int tb0 = blockIdx.x * 32, o0 = blockIdx.y * 32;
    float acc00 = 0.f, acc01 = 0.f, acc10 = 0.f, acc11 = 0.f;
    for (int kt = 0; kt < 768; kt += 32) {
        for (int l = threadIdx.x; l < 1024; l += 256) {
            int mi = l >> 5, ki = l & 31;
            int k = kt + ki;
            int tb = tb0 + mi;
            float av = (k < 512) ? g_hall[(size_t)tb * HH + k]
                                 : g_rwall[(size_t)tb * (RR * WWD) + (k - 512)];
            As[mi][ki] = av;
            Bs[mi][ki] = Wout[(size_t)(o0 + mi) * 768 + k];
        }
        __syncthreads();
        #pragma unroll 8
        for (int ki = 0; ki < 32; ki++) {
            float a0 = As[ty * 2][ki], a1 = As[ty * 2 + 1][ki];
            float b0 = Bs[tx * 2][ki], b1 = Bs[tx * 2 + 1][ki];
            acc00 += a0 * b0; acc01 += a0 * b1;
            acc10 += a1 * b0; acc11 += a1 * b1;
        }
        __syncthreads();
    }
    int tb = tb0 + ty * 2, o = o0 + tx * 2;
    float bo0 = bout[o], bo1 = bout[o + 1];
    out[(size_t)tb * OUTD + o] = acc00 + bo0;
    out[(size_t)tb * OUTD + o + 1] = acc01 + bo1;
    out[(size_t)(tb + 1) * OUTD + o] = acc10 + bo0;
    out[(size_t)(tb + 1) * OUTD + o + 1] = acc11 + bo1;
}

// -------------------- host launch --------------------
extern "C" void kernel_launch(void* const* d_in, const int* in_sizes, int n_in,
                              void* d_out, int out_size) {
    const float* x    = (const float*)d_in[0];
    const float* Wih  = (const float*)d_in[1];
    const float* Whh  = (const float*)d_in[2];
    const float* bih  = (const float*)d_in[3];
    const float* bhh  = (const float*)d_in[4];
    const float* Wint = (const float*)d_in[5];
    const float* bint = (const float*)d_in[6];
    const float* Wout = (const float*)d_in[7];
    const float* bout = (const float*)d_in[8];
    float* out = (float*)d_out;

    void* p;
    cudaGetSymbolAddress(&p, g_act);   cudaMemsetAsync(p, 0, sizeof(float) * 2 * BB * RLEN);
    cudaGetSymbolAddress(&p, g_c);     cudaMemsetAsync(p, 0, sizeof(float) * BB * HH);
    cudaGetSymbolAddress(&p, g_M);     cudaMemsetAsync(p, 0, sizeof(float) * 2 * BB * NN * WWD);
    cudaGetSymbolAddress(&p, g_usage); cudaMemsetAsync(p, 0, sizeof(float) * 2 * BB * NN);
    cudaGetSymbolAddress(&p, g_link);  cudaMemsetAsync(p, 0, sizeof(float) * BB * NN * NN);
    cudaGetSymbolAddress(&p, g_prec);  cudaMemsetAsync(p, 0, sizeof(float) * 2 * BB * NN);
    cudaGetSymbolAddress(&p, g_wr);    cudaMemsetAsync(p, 0, sizeof(float) * BB * RR * NN);
    cudaGetSymbolAddress(&p, g_ww);    cudaMemsetAsync(p, 0, sizeof(float) * 2 * BB * NN);

    k_transpose<<<(ITFD * HH + 255) / 256, 256>>>(Wint);
    k_prep_wrec<<<(G4H * RLEN + 255) / 256, 256>>>(Wih, Whh);
    k_gatesx<<<dim3(32, 64), 256>>>(x, Wih, bih, bhh);

    for (int t = 0; t < TT; t++) {
        int par = t & 1;
        k_lstm<<<512, 256>>>(t, par);
        k_itf2<<<118, 256>>>(bint, par);
        k_memw<<<256, 256>>>(par);
        k_read3<<<dim3(16, 4), 256>>>(t, par);
    }
    k_out<<<dim3(32, 8), 256>>>(Wout, bout, out);
}